// round 10
// baseline (speedup 1.0000x reference)
#include <cuda_runtime.h>
#include <cuda_bf16.h>
#include <cstdint>

#define HNUM 112
#define WNUM 112
#define HW   12544      // 112*112
#define BNUM 2
#define CIN  256
#define CMID 128
#define DNUM 49
#define RAD  3

#define NT 128          // pixel (N) tile in GEMM
#define KC 64           // K chunk

#if defined(__CUDA_ARCH_FEAT_SM103_ALL) || defined(__CUDA_ARCH_FEAT_SM100_ALL) || defined(__CUDA_ARCH_FEAT_SM101_ALL)
#define HAS_TCGEN05 1
#endif

// -------- scratch (no allocations allowed) --------
__device__ __nv_bfloat16 g_Ah[2][CMID * CIN];          // [tensor][m][k] bf16 hi
__device__ __nv_bfloat16 g_Al[2][CMID * CIN];          // [tensor][m][k] bf16 lo
__device__ float g_qk[2][(size_t)BNUM * HW * CMID];    // [tensor][b*HW][128], l2-normalized
__device__ float g_corr[(size_t)BNUM * DNUM * HW];     // [b][d][hw]

// ================= helpers =================
__device__ __forceinline__ uint32_t smem_u32(const void* p) {
    uint32_t a;
    asm("{ .reg .u64 t; cvta.to.shared.u64 t, %1; cvt.u32.u64 %0, t; }" : "=r"(a) : "l"(p));
    return a;
}
#define SW128(o) ((o) ^ (((o) >> 3) & 0x70))

#ifdef HAS_TCGEN05
__device__ __forceinline__ uint32_t elect_one() {
    uint32_t pred;
    asm volatile("{ .reg .pred p; elect.sync _|p, 0xFFFFFFFF; selp.b32 %0, 1, 0, p; }" : "=r"(pred));
    return pred;
}

static constexpr uint64_t DESC_BASE_SW128 =
    (uint64_t(2) << 61) | (uint64_t(1) << 46) | (uint64_t(64) << 32) | (uint64_t(1) << 16);
__device__ __forceinline__ uint64_t make_desc(uint32_t addr) {
    return DESC_BASE_SW128 | ((uint64_t)(addr >> 4) & 0x3FFF);
}

// idesc: dtype=F32, atype=btype=BF16, N=128, M=128
static constexpr uint32_t GEMM_IDESC =
    (1u << 4) | (1u << 7) | (1u << 10) | ((128u / 8) << 17) | ((128u / 16) << 24);

__device__ __forceinline__ void mma_f16_ss(uint32_t d, uint64_t ad, uint64_t bd,
                                           uint32_t idesc, uint32_t en) {
    asm volatile(
        "{\n\t.reg .pred p;\n\t"
        "setp.ne.u32 p, %4, 0;\n\t"
        "tcgen05.mma.cta_group::1.kind::f16 [%0], %1, %2, %3, {%5,%5,%5,%5}, p;\n\t}"
        :: "r"(d), "l"(ad), "l"(bd), "r"(idesc), "r"(en), "r"(0u) : "memory");
}

#define TC_ALLOC(sm_addr, ncols) \
    asm volatile("tcgen05.alloc.cta_group::1.sync.aligned.shared::cta.b32 [%0], %1;" \
                 :: "r"(sm_addr), "r"((uint32_t)(ncols)) : "memory")
#define TC_DEALLOC(tm, ncols) \
    asm volatile("tcgen05.dealloc.cta_group::1.sync.aligned.b32 %0, %1;" :: "r"(tm), "r"((uint32_t)(ncols)))
#define TC_RELINQ() asm volatile("tcgen05.relinquish_alloc_permit.cta_group::1.sync.aligned;")
#define TC_COMMIT(mbar) \
    asm volatile("tcgen05.commit.cta_group::1.mbarrier::arrive::one.shared::cluster.b64 [%0];" \
                 :: "r"(mbar) : "memory")
#define TC_FENCE_AFTER()  asm volatile("tcgen05.fence::after_thread_sync;" ::: "memory")
#define TC_FENCE_BEFORE() asm volatile("tcgen05.fence::before_thread_sync;" ::: "memory")
#define TC_WAIT_LD()      asm volatile("tcgen05.wait::ld.sync.aligned;" ::: "memory")
// generic-proxy smem writes -> async-proxy (tcgen05 MMA) visibility. REQUIRED.
#define FENCE_PROXY_ASYNC() asm volatile("fence.proxy.async.shared::cta;" ::: "memory")

#define MBAR_INIT(a, n) \
    asm volatile("mbarrier.init.shared.b64 [%0], %1;" :: "r"(a), "r"((uint32_t)(n)) : "memory")

#define MBAR_WAIT(mbar_addr, par) do {                                              \
    uint32_t _m = (mbar_addr), _p = (par), _done;                                   \
    asm volatile("{ .reg .pred p; mbarrier.try_wait.parity.acquire.cta.shared::cta.b64 p, [%1], %2; selp.b32 %0, 1, 0, p; }" \
        : "=r"(_done) : "r"(_m), "r"(_p) : "memory");                               \
    if (!_done) {                                                                   \
        asm volatile("{ .reg .pred P1; WL_%=: mbarrier.try_wait.parity.acquire.cta.shared::cta.b64 P1, [%0], %1, 0x989680; @P1 bra.uni WD_%=; bra.uni WL_%=; WD_%=: }" \
            :: "r"(_m), "r"(_p) : "memory");                                        \
    }                                                                               \
} while (0)

#define LDTM_X32(r, addr) \
    asm volatile("tcgen05.ld.sync.aligned.32x32b.x32.b32 " \
        "{%0,%1,%2,%3,%4,%5,%6,%7,%8,%9,%10,%11,%12,%13,%14,%15," \
        "%16,%17,%18,%19,%20,%21,%22,%23,%24,%25,%26,%27,%28,%29,%30,%31}, [%32];" \
        : "=r"((r)[0]),"=r"((r)[1]),"=r"((r)[2]),"=r"((r)[3]),"=r"((r)[4]),"=r"((r)[5]),"=r"((r)[6]),"=r"((r)[7]), \
          "=r"((r)[8]),"=r"((r)[9]),"=r"((r)[10]),"=r"((r)[11]),"=r"((r)[12]),"=r"((r)[13]),"=r"((r)[14]),"=r"((r)[15]), \
          "=r"((r)[16]),"=r"((r)[17]),"=r"((r)[18]),"=r"((r)[19]),"=r"((r)[20]),"=r"((r)[21]),"=r"((r)[22]),"=r"((r)[23]), \
          "=r"((r)[24]),"=r"((r)[25]),"=r"((r)[26]),"=r"((r)[27]),"=r"((r)[28]),"=r"((r)[29]),"=r"((r)[30]),"=r"((r)[31]) \
        : "r"(addr))
#endif // HAS_TCGEN05

// ---------------------------------------------------------------
// K0: split Wq/Wk into bf16 hi/lo ([m][k], k contiguous)
// ---------------------------------------------------------------
__global__ void k_prep(const float* __restrict__ Wq, const float* __restrict__ Wk) {
    int id = blockIdx.x * blockDim.x + threadIdx.x;
    if (id < CMID * CIN) {
        float a = Wq[id];
        __nv_bfloat16 h = __float2bfloat16_rn(a);
        g_Ah[0][id] = h;
        g_Al[0][id] = __float2bfloat16_rn(a - __bfloat162float(h));
        float b = Wk[id];
        __nv_bfloat16 h2 = __float2bfloat16_rn(b);
        g_Ah[1][id] = h2;
        g_Al[1][id] = __float2bfloat16_rn(b - __bfloat162float(h2));
    }
}

// ---------------------------------------------------------------
// K1: projection GEMM + fused per-pixel l2norm.
// Single 128-col TMEM accumulator; proxy-fenced staging; register-prefetch
// pipelining (next chunk's LDGs issue before waiting on prev MMA).
// ---------------------------------------------------------------
#define GEMM_SMEM 67584

__global__ __launch_bounds__(256) void k_gemm(const float* __restrict__ phi_cur,
                                              const float* __restrict__ phi_rnd) {
    extern __shared__ char smraw[];
    const int t = threadIdx.x;
    const int tsel = blockIdx.z, b = blockIdx.y;
    const int p0 = blockIdx.x * NT;

    const float* __restrict__ X = (tsel ? phi_rnd : phi_cur) + (size_t)b * CIN * HW;
    const __nv_bfloat16* __restrict__ Agh = g_Ah[tsel];
    const __nv_bfloat16* __restrict__ Agl = g_Al[tsel];

#ifdef HAS_TCGEN05
    const uint32_t sraw = smem_u32(smraw);
    const uint32_t sb = (sraw + 1023) & ~1023u;
    float* tb = (float*)(smraw + (sb - sraw));        // epilogue transpose buffer

    const uint32_t Ah = sb, Al = sb + 16384, Bh = sb + 32768, Bl = sb + 49152;
    const uint32_t HDR = sb + 66304;                  // tmem ptr
    const uint32_t MBAR = HDR + 8;
    const int wid = t >> 5;

    if (t == 0) MBAR_INIT(MBAR, 1);
    if (wid == 0) TC_ALLOC(HDR, 128);
    __syncthreads();
    uint32_t tmem;
    asm volatile("ld.shared.b32 %0, [%1];" : "=r"(tmem) : "r"(HDR));

    float    bx[32];            // prefetched X values (B tile)
    uint32_t avh[16], avl[16];  // prefetched A hi/lo packed pairs

    // ---- prefetch chunk 0 ----
#pragma unroll
    for (int i = 0; i < 16; i++) {
        int id = t + i * 256;
        int m = id >> 5, q = id & 31;
        avh[i] = *(const uint32_t*)(Agh + m * CIN + 0 + q * 2);
        avl[i] = *(const uint32_t*)(Agl + m * CIN + 0 + q * 2);
    }
#pragma unroll
    for (int i = 0; i < 32; i++) {
        int id = t + i * 256;
        int p = id & 127, c = id >> 7;
        bx[i] = X[(size_t)c * HW + p0 + p];
    }

    for (int ch = 0; ch < CIN / KC; ch++) {
        if (ch > 0) MBAR_WAIT(MBAR, (ch - 1) & 1);

        // ---- store staged chunk from registers ----
#pragma unroll
        for (int i = 0; i < 16; i++) {
            int id = t + i * 256;
            int m = id >> 5, q = id & 31;
            uint32_t off = SW128((uint32_t)(m * 128 + q * 4));
            asm volatile("st.shared.b32 [%0], %1;" :: "r"(Ah + off), "r"(avh[i]));
            asm volatile("st.shared.b32 [%0], %1;" :: "r"(Al + off), "r"(avl[i]));
        }
#pragma unroll
        for (int i = 0; i < 32; i++) {
            int id = t + i * 256;
            int p = id & 127, c = id >> 7;
            float x = bx[i];
            __nv_bfloat16 h = __float2bfloat16_rn(x);
            __nv_bfloat16 l = __float2bfloat16_rn(x - __bfloat162float(h));
            uint32_t off = SW128((uint32_t)(p * 128 + c * 2));
            unsigned short hu = __bfloat16_as_ushort(h);
            unsigned short lu = __bfloat16_as_ushort(l);
            asm volatile("st.shared.b16 [%0], %1;" :: "r"(Bh + off), "h"(hu));
            asm volatile("st.shared.b16 [%0], %1;" :: "r"(Bl + off), "h"(lu));
        }
        FENCE_PROXY_ASYNC();
        __syncthreads();

        if (wid == 0 && elect_one()) {
            uint64_t adh = make_desc(Ah), adl = make_desc(Al);
            uint64_t bdh = make_desc(Bh), bdl = make_desc(Bl);
#pragma unroll
            for (int ks = 0; ks < 4; ks++) {   // K=16 per MMA
                uint32_t en0 = (ch > 0 || ks > 0) ? 1u : 0u;
                mma_f16_ss(tmem, adh + ks * 2, bdh + ks * 2, GEMM_IDESC, en0);
                mma_f16_ss(tmem, adh + ks * 2, bdl + ks * 2, GEMM_IDESC, 1u);
                mma_f16_ss(tmem, adl + ks * 2, bdh + ks * 2, GEMM_IDESC, 1u);
            }
            TC_COMMIT(MBAR);
        }

        // ---- prefetch next chunk while this chunk's MMA runs ----
        if (ch < CIN / KC - 1) {
            const int c0n = (ch + 1) * KC;
#pragma unroll
            for (int i = 0; i < 16; i++) {
                int id = t + i * 256;
                int m = id >> 5, q = id & 31;
                avh[i] = *(const uint32_t*)(Agh + m * CIN + c0n + q * 2);
                avl[i] = *(const uint32_t*)(Agl + m * CIN + c0n + q * 2);
            }
#pragma unroll
            for (int i = 0; i < 32; i++) {
                int id = t + i * 256;
                int p = id & 127, c = id >> 7;
                bx[i] = X[(size_t)(c0n + c) * HW + p0 + p];
            }
        }
    }
    MBAR_WAIT(MBAR, (CIN / KC - 1) & 1);

    // ---- epilogue: LDTM -> smem transpose -> per-pixel l2norm -> pixel-major out ----
    TC_FENCE_AFTER();
    const int sub = wid & 3, half = wid >> 2;
    const int lane = t & 31;
    const int m = sub * 32 + lane;

    uint32_t d0[32], d1[32];
    LDTM_X32(d0, tmem + half * 64);
    LDTM_X32(d1, tmem + half * 64 + 32);
    TC_WAIT_LD();
    TC_FENCE_BEFORE();
    __syncthreads();     // stage buffers dead; tb overwrites them

#pragma unroll
    for (int j = 0; j < 32; j++) tb[m * 129 + half * 64 + j]      = __uint_as_float(d0[j]);
#pragma unroll
    for (int j = 0; j < 32; j++) tb[m * 129 + half * 64 + 32 + j] = __uint_as_float(d1[j]);
    __syncthreads();

    {
        const int p = t >> 1, hh = t & 1;
        float s = 0.f;
#pragma unroll
        for (int mm = 0; mm < 64; mm++) {
            float v = tb[(hh * 64 + mm) * 129 + p];
            s += v * v;
        }
        s += __shfl_xor_sync(0xffffffffu, s, 1);
        float sc = 1.f / fmaxf(sqrtf(s), 1e-12f);
        float* OUT = g_qk[tsel] + ((size_t)b * HW + p0 + p) * CMID + hh * 64;
#pragma unroll
        for (int j = 0; j < 64; j += 4) {
            float4 v;
            v.x = tb[(hh * 64 + j + 0) * 129 + p] * sc;
            v.y = tb[(hh * 64 + j + 1) * 129 + p] * sc;
            v.z = tb[(hh * 64 + j + 2) * 129 + p] * sc;
            v.w = tb[(hh * 64 + j + 3) * 129 + p] * sc;
            *(float4*)(OUT + j) = v;
        }
    }
    __syncthreads();
    if (wid == 0) {
        TC_RELINQ();
        TC_DEALLOC(tmem, 128);
    }
#else
    // ---------- SIMT fallback (generic gencode pass; not selected on GB300) ----------
    float* Ws = (float*)smraw;
    float* Xs = Ws + 16 * 128;
    float* red = Xs + 16 * 128;
    float* scale_s = red + 16 * 128;

    const int to = t >> 4, tp = t & 15;
    const int m0 = to * 8, q0 = tp * 8;

    float acc[8][8];
#pragma unroll
    for (int i = 0; i < 8; i++)
#pragma unroll
        for (int j = 0; j < 8; j++) acc[i][j] = 0.f;

    for (int c0 = 0; c0 < CIN; c0 += 16) {
#pragma unroll
        for (int i = 0; i < 8; i++) {
            int id = t + i * 256;
            int c = id >> 7, m = id & 127;
            Ws[c * 128 + m] = __bfloat162float(Agh[m * CIN + c0 + c]) +
                              __bfloat162float(Agl[m * CIN + c0 + c]);
            Xs[c * 128 + m] = X[(size_t)(c0 + c) * HW + p0 + m];
        }
        __syncthreads();
#pragma unroll
        for (int cc = 0; cc < 16; cc++) {
            float wv[8], xv[8];
#pragma unroll
            for (int i = 0; i < 8; i++) wv[i] = Ws[cc * 128 + m0 + i];
#pragma unroll
            for (int j = 0; j < 8; j++) xv[j] = Xs[cc * 128 + q0 + j];
#pragma unroll
            for (int i = 0; i < 8; i++)
#pragma unroll
                for (int j = 0; j < 8; j++) acc[i][j] += wv[i] * xv[j];
        }
        __syncthreads();
    }

#pragma unroll
    for (int j = 0; j < 8; j++) {
        float s = 0.f;
#pragma unroll
        for (int i = 0; i < 8; i++) s += acc[i][j] * acc[i][j];
        red[to * 128 + q0 + j] = s;
    }
    __syncthreads();
    if (t < 128) {
        float n = 0.f;
#pragma unroll
        for (int g = 0; g < 16; g++) n += red[g * 128 + t];
        scale_s[t] = 1.f / fmaxf(sqrtf(n), 1e-12f);
    }
    __syncthreads();

#pragma unroll
    for (int j = 0; j < 8; j++) {
        float sc = scale_s[q0 + j];
        float* dst = g_qk[tsel] + ((size_t)b * HW + p0 + q0 + j) * CMID + m0;
#pragma unroll
        for (int i = 0; i < 8; i++) dst[i] = acc[i][j] * sc;
    }
#endif
}

// ---------------------------------------------------------------
// K2: local correlation. 512 threads = 64 px x 8 d-groups (d = grp+8k,
// k<7) -> 6272 resident warps chip-wide (2x round-9), halving per-thread
// serial LDS+FMA work.
// ---------------------------------------------------------------
__global__ __launch_bounds__(512) void k_corr() {
    const int tx = blockIdx.x, ty = blockIdx.y, b = blockIdx.z;
    const int t   = threadIdx.x;
    const int pix = t & 63;
    const int grp = t >> 6;       // 0..7
    const int px  = pix & 7;
    const int py  = pix >> 3;

    __shared__ float ks[16][196];

    const float* __restrict__ Q = g_qk[0] + (size_t)b * HW * CMID;
    const float* __restrict__ K = g_qk[1] + (size_t)b * HW * CMID;

    const int gx = tx * 8 + px;
    const int gy = ty * 8 + py;
    const int pb = py * 14 + px;

    int addr[7];
#pragma unroll
    for (int k = 0; k < 7; k++) {
        int d  = grp + 8 * k;
        int dd = (d < DNUM) ? d : 0;
        addr[k] = pb + (dd / 7) * 14 + (dd % 7);
    }

    float acc[7];
#pragma unroll
    for (int k = 0; k < 7; k++) acc[k] = 0.f;

    const float* __restrict__ qptr = Q + (size_t)(gy * WNUM + gx) * CMID;

    for (int c0 = 0; c0 < CMID; c0 += 16) {
#pragma unroll
        for (int i = 0; i < 2; i++) {
            int id = t + i * 512;
            if (id < 784) {                 // 196 px * 4 float4-chunks
                int hp = id >> 2;
                int cv = id & 3;
                int hy = hp / 14, hx = hp - hy * 14;
                int sy = ty * 8 + hy - RAD;
                int sx = tx * 8 + hx - RAD;
                float4 v = make_float4(0.f, 0.f, 0.f, 0.f);
                if ((unsigned)sy < (unsigned)HNUM && (unsigned)sx < (unsigned)WNUM)
                    v = *(const float4*)(K + (size_t)(sy * WNUM + sx) * CMID + c0 + cv * 4);
                ks[cv * 4 + 0][hp] = v.x;
                ks[cv * 4 + 1][hp] = v.y;
                ks[cv * 4 + 2][hp] = v.z;
                ks[cv * 4 + 3][hp] = v.w;
            }
        }
        __syncthreads();

        float qr[16];
#pragma unroll
        for (int i = 0; i < 4; i++)
            *(float4*)&qr[i * 4] = *(const float4*)(qptr + c0 + i * 4);

#pragma unroll
        for (int cc = 0; cc < 16; cc++) {
            float qc = qr[cc];
#pragma unroll
            for (int k = 0; k < 7; k++)
                acc[k] += qc * ks[cc][addr[k]];
        }
        __syncthreads();
    }

    const int hw = gy * WNUM + gx;
#pragma unroll
    for (int k = 0; k < 7; k++) {
        int d = grp + 8 * k;
        if (d < DNUM)
            g_corr[((size_t)b * DNUM + d) * HW + hw] = acc[k];
    }
}

// ---------------------------------------------------------------
// K3: vol = Wv@corr + bv, geometry, softmax, du/dv/conf.
// 8 threads/pixel: thread q owns logits [8q, 8q+8) (Wv rows padded to 64 ->
// 32B-aligned float4 segments). 200K threads -> occupancy cap 66%.
// ---------------------------------------------------------------
__global__ __launch_bounds__(256) void k_final(const float* __restrict__ P_cur,
                                               const float* __restrict__ P_rnd,
                                               const float* __restrict__ Wv,
                                               const float* __restrict__ bv,
                                               const float* __restrict__ gamma_p,
                                               float* __restrict__ out) {
    __shared__ float Wvt[49 * 64];     // [d][e], e padded to 64 (pad = 0)
    __shared__ float bvs[64];
    const int t = threadIdx.x;
    for (int id = t; id < 49 * 64; id += 256) {
        int d = id >> 6, e = id & 63;
        Wvt[id] = (e < 49) ? Wv[e * 49 + d] : 0.f;
    }
    if (t < 64) bvs[t] = (t < 49) ? bv[t] : -3.0e38f;
    __syncthreads();

    const int q  = t & 7;                  // 0..7
    const int pl = t >> 3;                 // 0..31
    const int pixg = blockIdx.x * 32 + pl;
    const int b  = pixg / HW;
    const int hw = pixg - b * HW;
    const int h  = hw / WNUM;
    const int w  = hw - h * WNUM;
    const float gamma = *gamma_p;
    const int e0 = q * 8;

    const float* __restrict__ Pc = P_cur + (size_t)b * 3 * HW;
    const float* __restrict__ Pr = P_rnd + (size_t)b * 3 * HW;
    const float pcx = Pc[hw], pcy = Pc[HW + hw], pcz = Pc[2 * HW + hw];

    float l[8];
#pragma unroll
    for (int i = 0; i < 8; i++) {
        int e = e0 + i;
        if (e < 49) {
            int iy = e / 7, ix = e - iy * 7;
            int sy = h + iy - RAD, sx = w + ix - RAD;
            float prx = 0.f, pry = 0.f, prz = 0.f;
            if ((unsigned)sy < (unsigned)HNUM && (unsigned)sx < (unsigned)WNUM) {
                int o = sy * WNUM + sx;
                prx = Pr[o]; pry = Pr[HW + o]; prz = Pr[2 * HW + o];
            }
            float dx = pcx - prx, dy = pcy - pry, dz = pcz - prz;
            float ds = dx * dx + dy * dy + dz * dz;
            float dist = sqrtf(fmaxf(ds, 1e-12f));
            l[i] = bvs[e] + gamma * (-dist - 0.5f * fabsf(dz));
        } else {
            l[i] = -3.0e38f;
        }
    }

    const float* __restrict__ cb = g_corr + (size_t)b * DNUM * HW + hw;
    for (int d = 0; d < 49; d++) {
        float cd = cb[(size_t)d * HW];
        const float* wr = &Wvt[d * 64 + e0];
#pragma unroll
        for (int v4 = 0; v4 < 2; v4++) {
            float4 wv = *(const float4*)(wr + v4 * 4);
            l[v4 * 4 + 0] += wv.x * cd;
            l[v4 * 4 + 1] += wv.y * cd;
            l[v4 * 4 + 2] += wv.z * cd;
            l[v4 * 4 + 3] += wv.w * cd;
        }
    }

    float m = l[0];
#pragma unroll
    for (int i = 1; i < 8; i++) m = fmaxf(m, l[i]);
    m = fmaxf(m, __shfl_xor_sync(0xffffffffu, m, 1));
    m = fmaxf(m, __shfl_xor_sync(0xffffffffu, m, 2));
    m = fmaxf(m, __shfl_xor_sync(0xffffffffu, m, 4));

    float S = 0.f, du = 0.f, dv = 0.f;
#pragma unroll
    for (int i = 0; i < 8; i++) {
        int e = e0 + i;
        float ex = (e < 49) ? __expf(l[i] - m) : 0.f;
        S  += ex;
        du += ex * (float)(e % 7 - 3);
        dv += ex * (float)(e / 7 - 3);
    }
    S  += __shfl_xor_sync(0xffffffffu, S, 1);
    S  += __shfl_xor_sync(0xffffffffu, S, 2);
    S  += __shfl_xor_sync(0xffffffffu, S, 4);
    du += __shfl_xor_sync(0xffffffffu, du, 1);
    du += __shfl_xor_sync(0xffffffffu, du, 2);
    du += __shfl_xor_sync(0xffffffffu, du, 4);
    dv += __shfl_xor_sync(0xffffffffu, dv, 1);
    dv += __shfl_xor_sync(0xffffffffu, dv, 2);
    dv += __shfl_xor_sync(0xffffffffu, dv, 4);

    if (q == 0) {
        float inv = 1.f / S;
        out[pixg]                 = du * inv;
        out[BNUM * HW + pixg]     = dv * inv;
        out[2 * BNUM * HW + pixg] = inv;   // conf = exp(m-m)/S
    }
}

// ---------------------------------------------------------------
extern "C" void kernel_launch(void* const* d_in, const int* in_sizes, int n_in,
                              void* d_out, int out_size) {
    const float* phi_cur = (const float*)d_in[0];
    const float* phi_rnd = (const float*)d_in[1];
    const float* P_cur   = (const float*)d_in[2];
    const float* P_rnd   = (const float*)d_in[3];
    const float* Wq      = (const float*)d_in[4];
    const float* Wk      = (const float*)d_in[5];
    const float* Wv      = (const float*)d_in[6];
    const float* bv      = (const float*)d_in[7];
    const float* gamma   = (const float*)d_in[8];
    float* out = (float*)d_out;

    cudaFuncSetAttribute(k_gemm, cudaFuncAttributeMaxDynamicSharedMemorySize, GEMM_SMEM);

    k_prep<<<128, 256>>>(Wq, Wk);
    k_gemm<<<dim3(HW / NT, BNUM, 2), 256, GEMM_SMEM>>>(phi_cur, phi_rnd);
    k_corr<<<dim3(WNUM / 8, HNUM / 8, BNUM), 512>>>();
    k_final<<<(BNUM * HW) / 32, 256>>>(P_cur, P_rnd, Wv, bv, gamma, out);
}

// round 11
// speedup vs baseline: 1.1020x; 1.1020x over previous
#include <cuda_runtime.h>
#include <cuda_bf16.h>
#include <cstdint>

#define HNUM 112
#define WNUM 112
#define HW   12544      // 112*112
#define BNUM 2
#define CIN  256
#define CMID 128
#define DNUM 49
#define RAD  3

#define NT 128          // pixel (N) tile in GEMM
#define KC 64           // K chunk

#if defined(__CUDA_ARCH_FEAT_SM103_ALL) || defined(__CUDA_ARCH_FEAT_SM100_ALL) || defined(__CUDA_ARCH_FEAT_SM101_ALL)
#define HAS_TCGEN05 1
#endif

// -------- scratch (no allocations allowed) --------
__device__ __nv_bfloat16 g_Ah[2][CMID * CIN];          // [tensor][m][k] bf16 hi
__device__ __nv_bfloat16 g_Al[2][CMID * CIN];          // [tensor][m][k] bf16 lo
__device__ float g_qk[2][(size_t)BNUM * HW * CMID];    // [tensor][b*HW][128], l2-normalized
__device__ float g_corr[(size_t)BNUM * HW * 52];       // [b][hw][52] pixel-major, d 49..51 = 0

// ================= helpers =================
__device__ __forceinline__ uint32_t smem_u32(const void* p) {
    uint32_t a;
    asm("{ .reg .u64 t; cvta.to.shared.u64 t, %1; cvt.u32.u64 %0, t; }" : "=r"(a) : "l"(p));
    return a;
}
#define SW128(o) ((o) ^ (((o) >> 3) & 0x70))

#ifdef HAS_TCGEN05
__device__ __forceinline__ uint32_t elect_one() {
    uint32_t pred;
    asm volatile("{ .reg .pred p; elect.sync _|p, 0xFFFFFFFF; selp.b32 %0, 1, 0, p; }" : "=r"(pred));
    return pred;
}

static constexpr uint64_t DESC_BASE_SW128 =
    (uint64_t(2) << 61) | (uint64_t(1) << 46) | (uint64_t(64) << 32) | (uint64_t(1) << 16);
__device__ __forceinline__ uint64_t make_desc(uint32_t addr) {
    return DESC_BASE_SW128 | ((uint64_t)(addr >> 4) & 0x3FFF);
}

// idesc: dtype=F32, atype=btype=BF16, N=128, M=128
static constexpr uint32_t GEMM_IDESC =
    (1u << 4) | (1u << 7) | (1u << 10) | ((128u / 8) << 17) | ((128u / 16) << 24);

__device__ __forceinline__ void mma_f16_ss(uint32_t d, uint64_t ad, uint64_t bd,
                                           uint32_t idesc, uint32_t en) {
    asm volatile(
        "{\n\t.reg .pred p;\n\t"
        "setp.ne.u32 p, %4, 0;\n\t"
        "tcgen05.mma.cta_group::1.kind::f16 [%0], %1, %2, %3, {%5,%5,%5,%5}, p;\n\t}"
        :: "r"(d), "l"(ad), "l"(bd), "r"(idesc), "r"(en), "r"(0u) : "memory");
}

#define TC_ALLOC(sm_addr, ncols) \
    asm volatile("tcgen05.alloc.cta_group::1.sync.aligned.shared::cta.b32 [%0], %1;" \
                 :: "r"(sm_addr), "r"((uint32_t)(ncols)) : "memory")
#define TC_DEALLOC(tm, ncols) \
    asm volatile("tcgen05.dealloc.cta_group::1.sync.aligned.b32 %0, %1;" :: "r"(tm), "r"((uint32_t)(ncols)))
#define TC_RELINQ() asm volatile("tcgen05.relinquish_alloc_permit.cta_group::1.sync.aligned;")
#define TC_COMMIT(mbar) \
    asm volatile("tcgen05.commit.cta_group::1.mbarrier::arrive::one.shared::cluster.b64 [%0];" \
                 :: "r"(mbar) : "memory")
#define TC_FENCE_AFTER()  asm volatile("tcgen05.fence::after_thread_sync;" ::: "memory")
#define TC_FENCE_BEFORE() asm volatile("tcgen05.fence::before_thread_sync;" ::: "memory")
#define TC_WAIT_LD()      asm volatile("tcgen05.wait::ld.sync.aligned;" ::: "memory")
// generic-proxy smem writes -> async-proxy (tcgen05 MMA) visibility. REQUIRED.
#define FENCE_PROXY_ASYNC() asm volatile("fence.proxy.async.shared::cta;" ::: "memory")

#define MBAR_INIT(a, n) \
    asm volatile("mbarrier.init.shared.b64 [%0], %1;" :: "r"(a), "r"((uint32_t)(n)) : "memory")

#define MBAR_WAIT(mbar_addr, par) do {                                              \
    uint32_t _m = (mbar_addr), _p = (par), _done;                                   \
    asm volatile("{ .reg .pred p; mbarrier.try_wait.parity.acquire.cta.shared::cta.b64 p, [%1], %2; selp.b32 %0, 1, 0, p; }" \
        : "=r"(_done) : "r"(_m), "r"(_p) : "memory");                               \
    if (!_done) {                                                                   \
        asm volatile("{ .reg .pred P1; WL_%=: mbarrier.try_wait.parity.acquire.cta.shared::cta.b64 P1, [%0], %1, 0x989680; @P1 bra.uni WD_%=; bra.uni WL_%=; WD_%=: }" \
            :: "r"(_m), "r"(_p) : "memory");                                        \
    }                                                                               \
} while (0)

#define LDTM_X32(r, addr) \
    asm volatile("tcgen05.ld.sync.aligned.32x32b.x32.b32 " \
        "{%0,%1,%2,%3,%4,%5,%6,%7,%8,%9,%10,%11,%12,%13,%14,%15," \
        "%16,%17,%18,%19,%20,%21,%22,%23,%24,%25,%26,%27,%28,%29,%30,%31}, [%32];" \
        : "=r"((r)[0]),"=r"((r)[1]),"=r"((r)[2]),"=r"((r)[3]),"=r"((r)[4]),"=r"((r)[5]),"=r"((r)[6]),"=r"((r)[7]), \
          "=r"((r)[8]),"=r"((r)[9]),"=r"((r)[10]),"=r"((r)[11]),"=r"((r)[12]),"=r"((r)[13]),"=r"((r)[14]),"=r"((r)[15]), \
          "=r"((r)[16]),"=r"((r)[17]),"=r"((r)[18]),"=r"((r)[19]),"=r"((r)[20]),"=r"((r)[21]),"=r"((r)[22]),"=r"((r)[23]), \
          "=r"((r)[24]),"=r"((r)[25]),"=r"((r)[26]),"=r"((r)[27]),"=r"((r)[28]),"=r"((r)[29]),"=r"((r)[30]),"=r"((r)[31]) \
        : "r"(addr))
#endif // HAS_TCGEN05

// ---------------------------------------------------------------
// K0: split Wq/Wk into bf16 hi/lo ([m][k], k contiguous)
// ---------------------------------------------------------------
__global__ void k_prep(const float* __restrict__ Wq, const float* __restrict__ Wk) {
    int id = blockIdx.x * blockDim.x + threadIdx.x;
    if (id < CMID * CIN) {
        float a = Wq[id];
        __nv_bfloat16 h = __float2bfloat16_rn(a);
        g_Ah[0][id] = h;
        g_Al[0][id] = __float2bfloat16_rn(a - __bfloat162float(h));
        float b = Wk[id];
        __nv_bfloat16 h2 = __float2bfloat16_rn(b);
        g_Ah[1][id] = h2;
        g_Al[1][id] = __float2bfloat16_rn(b - __bfloat162float(h2));
    }
}

// ---------------------------------------------------------------
// K1: projection GEMM + fused per-pixel l2norm. (round-9 version)
// ---------------------------------------------------------------
#define GEMM_SMEM 67584

__global__ __launch_bounds__(256) void k_gemm(const float* __restrict__ phi_cur,
                                              const float* __restrict__ phi_rnd) {
    extern __shared__ char smraw[];
    const int t = threadIdx.x;
    const int tsel = blockIdx.z, b = blockIdx.y;
    const int p0 = blockIdx.x * NT;

    const float* __restrict__ X = (tsel ? phi_rnd : phi_cur) + (size_t)b * CIN * HW;
    const __nv_bfloat16* __restrict__ Agh = g_Ah[tsel];
    const __nv_bfloat16* __restrict__ Agl = g_Al[tsel];

#ifdef HAS_TCGEN05
    const uint32_t sraw = smem_u32(smraw);
    const uint32_t sb = (sraw + 1023) & ~1023u;
    float* tb = (float*)(smraw + (sb - sraw));        // epilogue transpose buffer

    const uint32_t Ah = sb, Al = sb + 16384, Bh = sb + 32768, Bl = sb + 49152;
    const uint32_t HDR = sb + 66304;                  // tmem ptr
    const uint32_t MBAR = HDR + 8;
    const int wid = t >> 5;

    if (t == 0) MBAR_INIT(MBAR, 1);
    if (wid == 0) TC_ALLOC(HDR, 128);
    __syncthreads();
    uint32_t tmem;
    asm volatile("ld.shared.b32 %0, [%1];" : "=r"(tmem) : "r"(HDR));

    float    bx[32];            // prefetched X values (B tile)
    uint32_t avh[16], avl[16];  // prefetched A hi/lo packed pairs

    // ---- prefetch chunk 0 ----
#pragma unroll
    for (int i = 0; i < 16; i++) {
        int id = t + i * 256;
        int m = id >> 5, q = id & 31;
        avh[i] = *(const uint32_t*)(Agh + m * CIN + 0 + q * 2);
        avl[i] = *(const uint32_t*)(Agl + m * CIN + 0 + q * 2);
    }
#pragma unroll
    for (int i = 0; i < 32; i++) {
        int id = t + i * 256;
        int p = id & 127, c = id >> 7;
        bx[i] = X[(size_t)c * HW + p0 + p];
    }

    for (int ch = 0; ch < CIN / KC; ch++) {
        if (ch > 0) MBAR_WAIT(MBAR, (ch - 1) & 1);

        // ---- store staged chunk from registers ----
#pragma unroll
        for (int i = 0; i < 16; i++) {
            int id = t + i * 256;
            int m = id >> 5, q = id & 31;
            uint32_t off = SW128((uint32_t)(m * 128 + q * 4));
            asm volatile("st.shared.b32 [%0], %1;" :: "r"(Ah + off), "r"(avh[i]));
            asm volatile("st.shared.b32 [%0], %1;" :: "r"(Al + off), "r"(avl[i]));
        }
#pragma unroll
        for (int i = 0; i < 32; i++) {
            int id = t + i * 256;
            int p = id & 127, c = id >> 7;
            float x = bx[i];
            __nv_bfloat16 h = __float2bfloat16_rn(x);
            __nv_bfloat16 l = __float2bfloat16_rn(x - __bfloat162float(h));
            uint32_t off = SW128((uint32_t)(p * 128 + c * 2));
            unsigned short hu = __bfloat16_as_ushort(h);
            unsigned short lu = __bfloat16_as_ushort(l);
            asm volatile("st.shared.b16 [%0], %1;" :: "r"(Bh + off), "h"(hu));
            asm volatile("st.shared.b16 [%0], %1;" :: "r"(Bl + off), "h"(lu));
        }
        FENCE_PROXY_ASYNC();
        __syncthreads();

        if (wid == 0 && elect_one()) {
            uint64_t adh = make_desc(Ah), adl = make_desc(Al);
            uint64_t bdh = make_desc(Bh), bdl = make_desc(Bl);
#pragma unroll
            for (int ks = 0; ks < 4; ks++) {   // K=16 per MMA
                uint32_t en0 = (ch > 0 || ks > 0) ? 1u : 0u;
                mma_f16_ss(tmem, adh + ks * 2, bdh + ks * 2, GEMM_IDESC, en0);
                mma_f16_ss(tmem, adh + ks * 2, bdl + ks * 2, GEMM_IDESC, 1u);
                mma_f16_ss(tmem, adl + ks * 2, bdh + ks * 2, GEMM_IDESC, 1u);
            }
            TC_COMMIT(MBAR);
        }

        // ---- prefetch next chunk while this chunk's MMA runs ----
        if (ch < CIN / KC - 1) {
            const int c0n = (ch + 1) * KC;
#pragma unroll
            for (int i = 0; i < 16; i++) {
                int id = t + i * 256;
                int m = id >> 5, q = id & 31;
                avh[i] = *(const uint32_t*)(Agh + m * CIN + c0n + q * 2);
                avl[i] = *(const uint32_t*)(Agl + m * CIN + c0n + q * 2);
            }
#pragma unroll
            for (int i = 0; i < 32; i++) {
                int id = t + i * 256;
                int p = id & 127, c = id >> 7;
                bx[i] = X[(size_t)(c0n + c) * HW + p0 + p];
            }
        }
    }
    MBAR_WAIT(MBAR, (CIN / KC - 1) & 1);

    // ---- epilogue: LDTM -> smem transpose -> per-pixel l2norm -> pixel-major out ----
    TC_FENCE_AFTER();
    const int sub = wid & 3, half = wid >> 2;
    const int lane = t & 31;
    const int m = sub * 32 + lane;

    uint32_t d0[32], d1[32];
    LDTM_X32(d0, tmem + half * 64);
    LDTM_X32(d1, tmem + half * 64 + 32);
    TC_WAIT_LD();
    TC_FENCE_BEFORE();
    __syncthreads();     // stage buffers dead; tb overwrites them

#pragma unroll
    for (int j = 0; j < 32; j++) tb[m * 129 + half * 64 + j]      = __uint_as_float(d0[j]);
#pragma unroll
    for (int j = 0; j < 32; j++) tb[m * 129 + half * 64 + 32 + j] = __uint_as_float(d1[j]);
    __syncthreads();

    {
        const int p = t >> 1, hh = t & 1;
        float s = 0.f;
#pragma unroll
        for (int mm = 0; mm < 64; mm++) {
            float v = tb[(hh * 64 + mm) * 129 + p];
            s += v * v;
        }
        s += __shfl_xor_sync(0xffffffffu, s, 1);
        float sc = 1.f / fmaxf(sqrtf(s), 1e-12f);
        float* OUT = g_qk[tsel] + ((size_t)b * HW + p0 + p) * CMID + hh * 64;
#pragma unroll
        for (int j = 0; j < 64; j += 4) {
            float4 v;
            v.x = tb[(hh * 64 + j + 0) * 129 + p] * sc;
            v.y = tb[(hh * 64 + j + 1) * 129 + p] * sc;
            v.z = tb[(hh * 64 + j + 2) * 129 + p] * sc;
            v.w = tb[(hh * 64 + j + 3) * 129 + p] * sc;
            *(float4*)(OUT + j) = v;
        }
    }
    __syncthreads();
    if (wid == 0) {
        TC_RELINQ();
        TC_DEALLOC(tmem, 128);
    }
#else
    // ---------- SIMT fallback (generic gencode pass; not selected on GB300) ----------
    float* Ws = (float*)smraw;
    float* Xs = Ws + 16 * 128;
    float* red = Xs + 16 * 128;
    float* scale_s = red + 16 * 128;

    const int to = t >> 4, tp = t & 15;
    const int m0 = to * 8, q0 = tp * 8;

    float acc[8][8];
#pragma unroll
    for (int i = 0; i < 8; i++)
#pragma unroll
        for (int j = 0; j < 8; j++) acc[i][j] = 0.f;

    for (int c0 = 0; c0 < CIN; c0 += 16) {
#pragma unroll
        for (int i = 0; i < 8; i++) {
            int id = t + i * 256;
            int c = id >> 7, m = id & 127;
            Ws[c * 128 + m] = __bfloat162float(Agh[m * CIN + c0 + c]) +
                              __bfloat162float(Agl[m * CIN + c0 + c]);
            Xs[c * 128 + m] = X[(size_t)(c0 + c) * HW + p0 + m];
        }
        __syncthreads();
#pragma unroll
        for (int cc = 0; cc < 16; cc++) {
            float wv[8], xv[8];
#pragma unroll
            for (int i = 0; i < 8; i++) wv[i] = Ws[cc * 128 + m0 + i];
#pragma unroll
            for (int j = 0; j < 8; j++) xv[j] = Xs[cc * 128 + q0 + j];
#pragma unroll
            for (int i = 0; i < 8; i++)
#pragma unroll
                for (int j = 0; j < 8; j++) acc[i][j] += wv[i] * xv[j];
        }
        __syncthreads();
    }

#pragma unroll
    for (int j = 0; j < 8; j++) {
        float s = 0.f;
#pragma unroll
        for (int i = 0; i < 8; i++) s += acc[i][j] * acc[i][j];
        red[to * 128 + q0 + j] = s;
    }
    __syncthreads();
    if (t < 128) {
        float n = 0.f;
#pragma unroll
        for (int g = 0; g < 16; g++) n += red[g * 128 + t];
        scale_s[t] = 1.f / fmaxf(sqrtf(n), 1e-12f);
    }
    __syncthreads();

#pragma unroll
    for (int j = 0; j < 8; j++) {
        float sc = scale_s[q0 + j];
        float* dst = g_qk[tsel] + ((size_t)b * HW + p0 + q0 + j) * CMID + m0;
#pragma unroll
        for (int i = 0; i < 8; i++) dst[i] = acc[i][j] * sc;
    }
#endif
}

// ---------------------------------------------------------------
// K2: local correlation (round-9 256-thr version) + smem transpose ->
// PIXEL-MAJOR output [b][hw][52] (d 49..51 zeroed) so k_final reads float4s.
// ---------------------------------------------------------------
__global__ __launch_bounds__(256) void k_corr() {
    const int tx = blockIdx.x, ty = blockIdx.y, b = blockIdx.z;
    const int t   = threadIdx.x;
    const int pix = t & 63;
    const int grp = t >> 6;
    const int px  = pix & 7;
    const int py  = pix >> 3;

    __shared__ float ks[16][196];
    __shared__ float corr_s[64 * 53];   // [pix][d], stride 53 (conflict-free)

    const float* __restrict__ Q = g_qk[0] + (size_t)b * HW * CMID;
    const float* __restrict__ K = g_qk[1] + (size_t)b * HW * CMID;

    const int gx = tx * 8 + px;
    const int gy = ty * 8 + py;
    const int pb = py * 14 + px;

    int addr[13];
#pragma unroll
    for (int k = 0; k < 13; k++) {
        int d  = grp + 4 * k;
        int dd = (d < DNUM) ? d : 0;
        addr[k] = pb + (dd / 7) * 14 + (dd % 7);
    }

    float acc[13];
#pragma unroll
    for (int k = 0; k < 13; k++) acc[k] = 0.f;

    const float* __restrict__ qptr = Q + (size_t)(gy * WNUM + gx) * CMID;

    for (int c0 = 0; c0 < CMID; c0 += 16) {
#pragma unroll
        for (int i = 0; i < 4; i++) {
            int id = t + i * 256;
            if (id < 784) {
                int hp = id >> 2;
                int cv = id & 3;
                int hy = hp / 14, hx = hp - hy * 14;
                int sy = ty * 8 + hy - RAD;
                int sx = tx * 8 + hx - RAD;
                float4 v = make_float4(0.f, 0.f, 0.f, 0.f);
                if ((unsigned)sy < (unsigned)HNUM && (unsigned)sx < (unsigned)WNUM)
                    v = *(const float4*)(K + (size_t)(sy * WNUM + sx) * CMID + c0 + cv * 4);
                ks[cv * 4 + 0][hp] = v.x;
                ks[cv * 4 + 1][hp] = v.y;
                ks[cv * 4 + 2][hp] = v.z;
                ks[cv * 4 + 3][hp] = v.w;
            }
        }
        __syncthreads();

        float qr[16];
#pragma unroll
        for (int i = 0; i < 4; i++)
            *(float4*)&qr[i * 4] = *(const float4*)(qptr + c0 + i * 4);

#pragma unroll
        for (int cc = 0; cc < 16; cc++) {
            float qc = qr[cc];
#pragma unroll
            for (int k = 0; k < 13; k++)
                acc[k] += qc * ks[cc][addr[k]];
        }
        __syncthreads();
    }

    // stash into smem transpose buffer; zero pads d=49..51
#pragma unroll
    for (int k = 0; k < 13; k++) {
        int d = grp + 4 * k;
        if (d < DNUM)
            corr_s[pix * 53 + d] = acc[k];
    }
    if (t < 192) corr_s[(t / 3) * 53 + 49 + (t % 3)] = 0.f;
    __syncthreads();

    // write pixel-major: 64 px * 13 float4 = 832 stores
    for (int id = t; id < 64 * 13; id += 256) {
        int p2 = id / 13;
        int j  = id - p2 * 13;
        int gy2 = ty * 8 + (p2 >> 3);
        int gx2 = tx * 8 + (p2 & 7);
        float4 v;
        v.x = corr_s[p2 * 53 + j * 4 + 0];
        v.y = corr_s[p2 * 53 + j * 4 + 1];
        v.z = corr_s[p2 * 53 + j * 4 + 2];
        v.w = corr_s[p2 * 53 + j * 4 + 3];
        *(float4*)(g_corr + ((size_t)b * HW + gy2 * WNUM + gx2) * 52 + j * 4) = v;
    }
}

// ---------------------------------------------------------------
// K3: vol = Wv@corr + bv, geometry, softmax, du/dv/conf.
// 4 thr/px (round-9 shape); corr read as 13 coalesced float4s per thread
// (pixel-major layout); Wvt padded to 52 rows (rows 49..51 = 0) so padded
// corr lanes contribute exactly 0.
// ---------------------------------------------------------------
__global__ __launch_bounds__(128) void k_final(const float* __restrict__ P_cur,
                                               const float* __restrict__ P_rnd,
                                               const float* __restrict__ Wv,
                                               const float* __restrict__ bv,
                                               const float* __restrict__ gamma_p,
                                               float* __restrict__ out) {
    __shared__ float Wvt[52 * 64];     // [d][e], d padded to 52 (zeros), e padded to 64 (zeros)
    __shared__ float bvs[64];
    const int t = threadIdx.x;
    for (int id = t; id < 52 * 64; id += 128) {
        int d = id >> 6, e = id & 63;
        Wvt[id] = (e < 49 && d < 49) ? Wv[e * 49 + d] : 0.f;
    }
    if (t < 64) bvs[t] = (t < 49) ? bv[t] : -3.0e38f;
    __syncthreads();

    const int q  = t & 3;
    const int pl = t >> 2;                  // 0..31
    const int pixg = blockIdx.x * 32 + pl;
    const int b  = pixg / HW;
    const int hw = pixg - b * HW;
    const int h  = hw / WNUM;
    const int w  = hw - h * WNUM;
    const float gamma = *gamma_p;
    const int e0 = q * 16;

    const float* __restrict__ Pc = P_cur + (size_t)b * 3 * HW;
    const float* __restrict__ Pr = P_rnd + (size_t)b * 3 * HW;
    const float pcx = Pc[hw], pcy = Pc[HW + hw], pcz = Pc[2 * HW + hw];

    float l[16];
#pragma unroll
    for (int i = 0; i < 16; i++) {
        int e = e0 + i;
        if (e < 49) {
            int iy = e / 7, ix = e - iy * 7;
            int sy = h + iy - RAD, sx = w + ix - RAD;
            float prx = 0.f, pry = 0.f, prz = 0.f;
            if ((unsigned)sy < (unsigned)HNUM && (unsigned)sx < (unsigned)WNUM) {
                int o = sy * WNUM + sx;
                prx = Pr[o]; pry = Pr[HW + o]; prz = Pr[2 * HW + o];
            }
            float dx = pcx - prx, dy = pcy - pry, dz = pcz - prz;
            float ds = dx * dx + dy * dy + dz * dz;
            float dist = sqrtf(fmaxf(ds, 1e-12f));
            l[i] = bvs[e] + gamma * (-dist - 0.5f * fabsf(dz));
        } else {
            l[i] = -3.0e38f;
        }
    }

    const float4* __restrict__ cb4 = (const float4*)(g_corr + (size_t)pixg * 52);
#pragma unroll
    for (int j = 0; j < 13; j++) {
        float4 c4 = cb4[j];
        float cds[4] = {c4.x, c4.y, c4.z, c4.w};
#pragma unroll
        for (int dd = 0; dd < 4; dd++) {
            int d = j * 4 + dd;
            float cd = cds[dd];
            const float* wr = &Wvt[d * 64 + e0];
#pragma unroll
            for (int v4 = 0; v4 < 4; v4++) {
                float4 wv = *(const float4*)(wr + v4 * 4);
                l[v4 * 4 + 0] += wv.x * cd;
                l[v4 * 4 + 1] += wv.y * cd;
                l[v4 * 4 + 2] += wv.z * cd;
                l[v4 * 4 + 3] += wv.w * cd;
            }
        }
    }

    float m = l[0];
#pragma unroll
    for (int i = 1; i < 16; i++) m = fmaxf(m, l[i]);
    m = fmaxf(m, __shfl_xor_sync(0xffffffffu, m, 1));
    m = fmaxf(m, __shfl_xor_sync(0xffffffffu, m, 2));

    float S = 0.f, du = 0.f, dv = 0.f;
#pragma unroll
    for (int i = 0; i < 16; i++) {
        int e = e0 + i;
        float ex = (e < 49) ? __expf(l[i] - m) : 0.f;
        S  += ex;
        du += ex * (float)(e % 7 - 3);
        dv += ex * (float)(e / 7 - 3);
    }
    S  += __shfl_xor_sync(0xffffffffu, S, 1);
    S  += __shfl_xor_sync(0xffffffffu, S, 2);
    du += __shfl_xor_sync(0xffffffffu, du, 1);
    du += __shfl_xor_sync(0xffffffffu, du, 2);
    dv += __shfl_xor_sync(0xffffffffu, dv, 1);
    dv += __shfl_xor_sync(0xffffffffu, dv, 2);

    if (q == 0) {
        float inv = 1.f / S;
        out[pixg]                 = du * inv;
        out[BNUM * HW + pixg]     = dv * inv;
        out[2 * BNUM * HW + pixg] = inv;   // conf = exp(m-m)/S
    }
}

// ---------------------------------------------------------------
extern "C" void kernel_launch(void* const* d_in, const int* in_sizes, int n_in,
                              void* d_out, int out_size) {
    const float* phi_cur = (const float*)d_in[0];
    const float* phi_rnd = (const float*)d_in[1];
    const float* P_cur   = (const float*)d_in[2];
    const float* P_rnd   = (const float*)d_in[3];
    const float* Wq      = (const float*)d_in[4];
    const float* Wk      = (const float*)d_in[5];
    const float* Wv      = (const float*)d_in[6];
    const float* bv      = (const float*)d_in[7];
    const float* gamma   = (const float*)d_in[8];
    float* out = (float*)d_out;

    cudaFuncSetAttribute(k_gemm, cudaFuncAttributeMaxDynamicSharedMemorySize, GEMM_SMEM);

    k_prep<<<128, 256>>>(Wq, Wk);
    k_gemm<<<dim3(HW / NT, BNUM, 2), 256, GEMM_SMEM>>>(phi_cur, phi_rnd);
    k_corr<<<dim3(WNUM / 8, HNUM / 8, BNUM), 256>>>();
    k_final<<<(BNUM * HW) / 32, 128>>>(P_cur, P_rnd, Wv, bv, gamma, out);
}

// round 12
// speedup vs baseline: 1.4822x; 1.3450x over previous
#include <cuda_runtime.h>
#include <cuda_bf16.h>
#include <cstdint>

#define HNUM 112
#define WNUM 112
#define HW   12544      // 112*112
#define BNUM 2
#define CIN  256
#define CMID 128
#define DNUM 49
#define RAD  3

#define NT 128          // pixel (N) tile in GEMM
#define KC 64           // K chunk

#if defined(__CUDA_ARCH_FEAT_SM103_ALL) || defined(__CUDA_ARCH_FEAT_SM100_ALL) || defined(__CUDA_ARCH_FEAT_SM101_ALL)
#define HAS_TCGEN05 1
#endif

// -------- scratch (no allocations allowed) --------
__device__ __nv_bfloat16 g_Ah[2][CMID * CIN];          // [tensor][m][k] bf16 hi
__device__ __nv_bfloat16 g_Al[2][CMID * CIN];          // [tensor][m][k] bf16 lo
__device__ float g_qk[2][(size_t)BNUM * HW * CMID];    // [tensor][b*HW][128], l2-normalized
__device__ float g_corr[(size_t)BNUM * HW * 52];       // [b][hw][52] pixel-major, d 49..51 = 0

// ================= helpers =================
__device__ __forceinline__ uint32_t smem_u32(const void* p) {
    uint32_t a;
    asm("{ .reg .u64 t; cvta.to.shared.u64 t, %1; cvt.u32.u64 %0, t; }" : "=r"(a) : "l"(p));
    return a;
}
#define SW128(o) ((o) ^ (((o) >> 3) & 0x70))

#ifdef HAS_TCGEN05
__device__ __forceinline__ uint32_t elect_one() {
    uint32_t pred;
    asm volatile("{ .reg .pred p; elect.sync _|p, 0xFFFFFFFF; selp.b32 %0, 1, 0, p; }" : "=r"(pred));
    return pred;
}

static constexpr uint64_t DESC_BASE_SW128 =
    (uint64_t(2) << 61) | (uint64_t(1) << 46) | (uint64_t(64) << 32) | (uint64_t(1) << 16);
__device__ __forceinline__ uint64_t make_desc(uint32_t addr) {
    return DESC_BASE_SW128 | ((uint64_t)(addr >> 4) & 0x3FFF);
}

// idesc: dtype=F32, atype=btype=BF16, N=128, M=128
static constexpr uint32_t GEMM_IDESC =
    (1u << 4) | (1u << 7) | (1u << 10) | ((128u / 8) << 17) | ((128u / 16) << 24);

__device__ __forceinline__ void mma_f16_ss(uint32_t d, uint64_t ad, uint64_t bd,
                                           uint32_t idesc, uint32_t en) {
    asm volatile(
        "{\n\t.reg .pred p;\n\t"
        "setp.ne.u32 p, %4, 0;\n\t"
        "tcgen05.mma.cta_group::1.kind::f16 [%0], %1, %2, %3, {%5,%5,%5,%5}, p;\n\t}"
        :: "r"(d), "l"(ad), "l"(bd), "r"(idesc), "r"(en), "r"(0u) : "memory");
}

#define TC_ALLOC(sm_addr, ncols) \
    asm volatile("tcgen05.alloc.cta_group::1.sync.aligned.shared::cta.b32 [%0], %1;" \
                 :: "r"(sm_addr), "r"((uint32_t)(ncols)) : "memory")
#define TC_DEALLOC(tm, ncols) \
    asm volatile("tcgen05.dealloc.cta_group::1.sync.aligned.b32 %0, %1;" :: "r"(tm), "r"((uint32_t)(ncols)))
#define TC_RELINQ() asm volatile("tcgen05.relinquish_alloc_permit.cta_group::1.sync.aligned;")
#define TC_COMMIT(mbar) \
    asm volatile("tcgen05.commit.cta_group::1.mbarrier::arrive::one.shared::cluster.b64 [%0];" \
                 :: "r"(mbar) : "memory")
#define TC_FENCE_AFTER()  asm volatile("tcgen05.fence::after_thread_sync;" ::: "memory")
#define TC_FENCE_BEFORE() asm volatile("tcgen05.fence::before_thread_sync;" ::: "memory")
#define TC_WAIT_LD()      asm volatile("tcgen05.wait::ld.sync.aligned;" ::: "memory")
// generic-proxy smem writes -> async-proxy (tcgen05 MMA) visibility. REQUIRED.
#define FENCE_PROXY_ASYNC() asm volatile("fence.proxy.async.shared::cta;" ::: "memory")

#define MBAR_INIT(a, n) \
    asm volatile("mbarrier.init.shared.b64 [%0], %1;" :: "r"(a), "r"((uint32_t)(n)) : "memory")

#define MBAR_WAIT(mbar_addr, par) do {                                              \
    uint32_t _m = (mbar_addr), _p = (par), _done;                                   \
    asm volatile("{ .reg .pred p; mbarrier.try_wait.parity.acquire.cta.shared::cta.b64 p, [%1], %2; selp.b32 %0, 1, 0, p; }" \
        : "=r"(_done) : "r"(_m), "r"(_p) : "memory");                               \
    if (!_done) {                                                                   \
        asm volatile("{ .reg .pred P1; WL_%=: mbarrier.try_wait.parity.acquire.cta.shared::cta.b64 P1, [%0], %1, 0x989680; @P1 bra.uni WD_%=; bra.uni WL_%=; WD_%=: }" \
            :: "r"(_m), "r"(_p) : "memory");                                        \
    }                                                                               \
} while (0)

#define LDTM_X32(r, addr) \
    asm volatile("tcgen05.ld.sync.aligned.32x32b.x32.b32 " \
        "{%0,%1,%2,%3,%4,%5,%6,%7,%8,%9,%10,%11,%12,%13,%14,%15," \
        "%16,%17,%18,%19,%20,%21,%22,%23,%24,%25,%26,%27,%28,%29,%30,%31}, [%32];" \
        : "=r"((r)[0]),"=r"((r)[1]),"=r"((r)[2]),"=r"((r)[3]),"=r"((r)[4]),"=r"((r)[5]),"=r"((r)[6]),"=r"((r)[7]), \
          "=r"((r)[8]),"=r"((r)[9]),"=r"((r)[10]),"=r"((r)[11]),"=r"((r)[12]),"=r"((r)[13]),"=r"((r)[14]),"=r"((r)[15]), \
          "=r"((r)[16]),"=r"((r)[17]),"=r"((r)[18]),"=r"((r)[19]),"=r"((r)[20]),"=r"((r)[21]),"=r"((r)[22]),"=r"((r)[23]), \
          "=r"((r)[24]),"=r"((r)[25]),"=r"((r)[26]),"=r"((r)[27]),"=r"((r)[28]),"=r"((r)[29]),"=r"((r)[30]),"=r"((r)[31]) \
        : "r"(addr))
#endif // HAS_TCGEN05

// ---------------------------------------------------------------
// K0: split Wq/Wk into bf16 hi/lo ([m][k], k contiguous)
// ---------------------------------------------------------------
__global__ void k_prep(const float* __restrict__ Wq, const float* __restrict__ Wk) {
    int id = blockIdx.x * blockDim.x + threadIdx.x;
    if (id < CMID * CIN) {
        float a = Wq[id];
        __nv_bfloat16 h = __float2bfloat16_rn(a);
        g_Ah[0][id] = h;
        g_Al[0][id] = __float2bfloat16_rn(a - __bfloat162float(h));
        float b = Wk[id];
        __nv_bfloat16 h2 = __float2bfloat16_rn(b);
        g_Ah[1][id] = h2;
        g_Al[1][id] = __float2bfloat16_rn(b - __bfloat162float(h2));
    }
}

// ---------------------------------------------------------------
// K1: projection GEMM + fused per-pixel l2norm. (round-9 version)
// ---------------------------------------------------------------
#define GEMM_SMEM 67584

__global__ __launch_bounds__(256) void k_gemm(const float* __restrict__ phi_cur,
                                              const float* __restrict__ phi_rnd) {
    extern __shared__ char smraw[];
    const int t = threadIdx.x;
    const int tsel = blockIdx.z, b = blockIdx.y;
    const int p0 = blockIdx.x * NT;

    const float* __restrict__ X = (tsel ? phi_rnd : phi_cur) + (size_t)b * CIN * HW;
    const __nv_bfloat16* __restrict__ Agh = g_Ah[tsel];
    const __nv_bfloat16* __restrict__ Agl = g_Al[tsel];

#ifdef HAS_TCGEN05
    const uint32_t sraw = smem_u32(smraw);
    const uint32_t sb = (sraw + 1023) & ~1023u;
    float* tb = (float*)(smraw + (sb - sraw));        // epilogue transpose buffer

    const uint32_t Ah = sb, Al = sb + 16384, Bh = sb + 32768, Bl = sb + 49152;
    const uint32_t HDR = sb + 66304;                  // tmem ptr
    const uint32_t MBAR = HDR + 8;
    const int wid = t >> 5;

    if (t == 0) MBAR_INIT(MBAR, 1);
    if (wid == 0) TC_ALLOC(HDR, 128);
    __syncthreads();
    uint32_t tmem;
    asm volatile("ld.shared.b32 %0, [%1];" : "=r"(tmem) : "r"(HDR));

    float    bx[32];            // prefetched X values (B tile)
    uint32_t avh[16], avl[16];  // prefetched A hi/lo packed pairs

    // ---- prefetch chunk 0 ----
#pragma unroll
    for (int i = 0; i < 16; i++) {
        int id = t + i * 256;
        int m = id >> 5, q = id & 31;
        avh[i] = *(const uint32_t*)(Agh + m * CIN + 0 + q * 2);
        avl[i] = *(const uint32_t*)(Agl + m * CIN + 0 + q * 2);
    }
#pragma unroll
    for (int i = 0; i < 32; i++) {
        int id = t + i * 256;
        int p = id & 127, c = id >> 7;
        bx[i] = X[(size_t)c * HW + p0 + p];
    }

    for (int ch = 0; ch < CIN / KC; ch++) {
        if (ch > 0) MBAR_WAIT(MBAR, (ch - 1) & 1);

        // ---- store staged chunk from registers ----
#pragma unroll
        for (int i = 0; i < 16; i++) {
            int id = t + i * 256;
            int m = id >> 5, q = id & 31;
            uint32_t off = SW128((uint32_t)(m * 128 + q * 4));
            asm volatile("st.shared.b32 [%0], %1;" :: "r"(Ah + off), "r"(avh[i]));
            asm volatile("st.shared.b32 [%0], %1;" :: "r"(Al + off), "r"(avl[i]));
        }
#pragma unroll
        for (int i = 0; i < 32; i++) {
            int id = t + i * 256;
            int p = id & 127, c = id >> 7;
            float x = bx[i];
            __nv_bfloat16 h = __float2bfloat16_rn(x);
            __nv_bfloat16 l = __float2bfloat16_rn(x - __bfloat162float(h));
            uint32_t off = SW128((uint32_t)(p * 128 + c * 2));
            unsigned short hu = __bfloat16_as_ushort(h);
            unsigned short lu = __bfloat16_as_ushort(l);
            asm volatile("st.shared.b16 [%0], %1;" :: "r"(Bh + off), "h"(hu));
            asm volatile("st.shared.b16 [%0], %1;" :: "r"(Bl + off), "h"(lu));
        }
        FENCE_PROXY_ASYNC();
        __syncthreads();

        if (wid == 0 && elect_one()) {
            uint64_t adh = make_desc(Ah), adl = make_desc(Al);
            uint64_t bdh = make_desc(Bh), bdl = make_desc(Bl);
#pragma unroll
            for (int ks = 0; ks < 4; ks++) {   // K=16 per MMA
                uint32_t en0 = (ch > 0 || ks > 0) ? 1u : 0u;
                mma_f16_ss(tmem, adh + ks * 2, bdh + ks * 2, GEMM_IDESC, en0);
                mma_f16_ss(tmem, adh + ks * 2, bdl + ks * 2, GEMM_IDESC, 1u);
                mma_f16_ss(tmem, adl + ks * 2, bdh + ks * 2, GEMM_IDESC, 1u);
            }
            TC_COMMIT(MBAR);
        }

        // ---- prefetch next chunk while this chunk's MMA runs ----
        if (ch < CIN / KC - 1) {
            const int c0n = (ch + 1) * KC;
#pragma unroll
            for (int i = 0; i < 16; i++) {
                int id = t + i * 256;
                int m = id >> 5, q = id & 31;
                avh[i] = *(const uint32_t*)(Agh + m * CIN + c0n + q * 2);
                avl[i] = *(const uint32_t*)(Agl + m * CIN + c0n + q * 2);
            }
#pragma unroll
            for (int i = 0; i < 32; i++) {
                int id = t + i * 256;
                int p = id & 127, c = id >> 7;
                bx[i] = X[(size_t)(c0n + c) * HW + p0 + p];
            }
        }
    }
    MBAR_WAIT(MBAR, (CIN / KC - 1) & 1);

    // ---- epilogue: LDTM -> smem transpose -> per-pixel l2norm -> pixel-major out ----
    TC_FENCE_AFTER();
    const int sub = wid & 3, half = wid >> 2;
    const int lane = t & 31;
    const int m = sub * 32 + lane;

    uint32_t d0[32], d1[32];
    LDTM_X32(d0, tmem + half * 64);
    LDTM_X32(d1, tmem + half * 64 + 32);
    TC_WAIT_LD();
    TC_FENCE_BEFORE();
    __syncthreads();     // stage buffers dead; tb overwrites them

#pragma unroll
    for (int j = 0; j < 32; j++) tb[m * 129 + half * 64 + j]      = __uint_as_float(d0[j]);
#pragma unroll
    for (int j = 0; j < 32; j++) tb[m * 129 + half * 64 + 32 + j] = __uint_as_float(d1[j]);
    __syncthreads();

    {
        const int p = t >> 1, hh = t & 1;
        float s = 0.f;
#pragma unroll
        for (int mm = 0; mm < 64; mm++) {
            float v = tb[(hh * 64 + mm) * 129 + p];
            s += v * v;
        }
        s += __shfl_xor_sync(0xffffffffu, s, 1);
        float sc = 1.f / fmaxf(sqrtf(s), 1e-12f);
        float* OUT = g_qk[tsel] + ((size_t)b * HW + p0 + p) * CMID + hh * 64;
#pragma unroll
        for (int j = 0; j < 64; j += 4) {
            float4 v;
            v.x = tb[(hh * 64 + j + 0) * 129 + p] * sc;
            v.y = tb[(hh * 64 + j + 1) * 129 + p] * sc;
            v.z = tb[(hh * 64 + j + 2) * 129 + p] * sc;
            v.w = tb[(hh * 64 + j + 3) * 129 + p] * sc;
            *(float4*)(OUT + j) = v;
        }
    }
    __syncthreads();
    if (wid == 0) {
        TC_RELINQ();
        TC_DEALLOC(tmem, 128);
    }
#else
    // ---------- SIMT fallback (generic gencode pass; not selected on GB300) ----------
    float* Ws = (float*)smraw;
    float* Xs = Ws + 16 * 128;
    float* red = Xs + 16 * 128;
    float* scale_s = red + 16 * 128;

    const int to = t >> 4, tp = t & 15;
    const int m0 = to * 8, q0 = tp * 8;

    float acc[8][8];
#pragma unroll
    for (int i = 0; i < 8; i++)
#pragma unroll
        for (int j = 0; j < 8; j++) acc[i][j] = 0.f;

    for (int c0 = 0; c0 < CIN; c0 += 16) {
#pragma unroll
        for (int i = 0; i < 8; i++) {
            int id = t + i * 256;
            int c = id >> 7, m = id & 127;
            Ws[c * 128 + m] = __bfloat162float(Agh[m * CIN + c0 + c]) +
                              __bfloat162float(Agl[m * CIN + c0 + c]);
            Xs[c * 128 + m] = X[(size_t)(c0 + c) * HW + p0 + m];
        }
        __syncthreads();
#pragma unroll
        for (int cc = 0; cc < 16; cc++) {
            float wv[8], xv[8];
#pragma unroll
            for (int i = 0; i < 8; i++) wv[i] = Ws[cc * 128 + m0 + i];
#pragma unroll
            for (int j = 0; j < 8; j++) xv[j] = Xs[cc * 128 + q0 + j];
#pragma unroll
            for (int i = 0; i < 8; i++)
#pragma unroll
                for (int j = 0; j < 8; j++) acc[i][j] += wv[i] * xv[j];
        }
        __syncthreads();
    }

#pragma unroll
    for (int j = 0; j < 8; j++) {
        float s = 0.f;
#pragma unroll
        for (int i = 0; i < 8; i++) s += acc[i][j] * acc[i][j];
        red[to * 128 + q0 + j] = s;
    }
    __syncthreads();
    if (t < 128) {
        float n = 0.f;
#pragma unroll
        for (int g = 0; g < 16; g++) n += red[g * 128 + t];
        scale_s[t] = 1.f / fmaxf(sqrtf(n), 1e-12f);
    }
    __syncthreads();

#pragma unroll
    for (int j = 0; j < 8; j++) {
        float sc = scale_s[q0 + j];
        float* dst = g_qk[tsel] + ((size_t)b * HW + p0 + q0 + j) * CMID + m0;
#pragma unroll
        for (int i = 0; i < 8; i++) dst[i] = acc[i][j] * sc;
    }
#endif
}

// ---------------------------------------------------------------
// K2: local correlation. QUAD layout: pix = t>>2, grp = t&3 (the 4 d-group
// threads of a pixel are adjacent lanes). Each lane loads ONE float4 of q
// per chunk (its grp's 4 channels) and the quad shares channels via
// width-4 shfl -> q gmem traffic drops 4x. Output pixel-major [b][hw][52].
// ---------------------------------------------------------------
__global__ __launch_bounds__(256) void k_corr() {
    const int tx = blockIdx.x, ty = blockIdx.y, b = blockIdx.z;
    const int t   = threadIdx.x;
    const int pix = t >> 2;       // 0..63
    const int grp = t & 3;        // 0..3
    const int px  = pix & 7;
    const int py  = pix >> 3;

    __shared__ float ks[16][196];
    __shared__ float corr_s[64 * 53];   // [pix][d], stride 53 (conflict-free)

    const float* __restrict__ Q = g_qk[0] + (size_t)b * HW * CMID;
    const float* __restrict__ K = g_qk[1] + (size_t)b * HW * CMID;

    const int gx = tx * 8 + px;
    const int gy = ty * 8 + py;
    const int pb = py * 14 + px;

    int addr[13];
#pragma unroll
    for (int k = 0; k < 13; k++) {
        int d  = grp + 4 * k;
        int dd = (d < DNUM) ? d : 0;
        addr[k] = pb + (dd / 7) * 14 + (dd % 7);
    }

    float acc[13];
#pragma unroll
    for (int k = 0; k < 13; k++) acc[k] = 0.f;

    const float* __restrict__ qptr = Q + (size_t)(gy * WNUM + gx) * CMID;

    for (int c0 = 0; c0 < CMID; c0 += 16) {
#pragma unroll
        for (int i = 0; i < 4; i++) {
            int id = t + i * 256;
            if (id < 784) {
                int hp = id >> 2;
                int cv = id & 3;
                int hy = hp / 14, hx = hp - hy * 14;
                int sy = ty * 8 + hy - RAD;
                int sx = tx * 8 + hx - RAD;
                float4 v = make_float4(0.f, 0.f, 0.f, 0.f);
                if ((unsigned)sy < (unsigned)HNUM && (unsigned)sx < (unsigned)WNUM)
                    v = *(const float4*)(K + (size_t)(sy * WNUM + sx) * CMID + c0 + cv * 4);
                ks[cv * 4 + 0][hp] = v.x;
                ks[cv * 4 + 1][hp] = v.y;
                ks[cv * 4 + 2][hp] = v.z;
                ks[cv * 4 + 3][hp] = v.w;
            }
        }
        __syncthreads();

        // one float4 of q per lane (grp-th quarter of this 16-ch chunk)
        float4 qv = *(const float4*)(qptr + c0 + grp * 4);
        float qa[4] = {qv.x, qv.y, qv.z, qv.w};

#pragma unroll
        for (int cc = 0; cc < 16; cc++) {
            float qc = __shfl_sync(0xffffffffu, qa[cc & 3], cc >> 2, 4);
#pragma unroll
            for (int k = 0; k < 13; k++)
                acc[k] += qc * ks[cc][addr[k]];
        }
        __syncthreads();
    }

    // stash into smem transpose buffer; zero pads d=49..51
#pragma unroll
    for (int k = 0; k < 13; k++) {
        int d = grp + 4 * k;
        if (d < DNUM)
            corr_s[pix * 53 + d] = acc[k];
    }
    if (t < 192) corr_s[(t / 3) * 53 + 49 + (t % 3)] = 0.f;
    __syncthreads();

    // write pixel-major: 64 px * 13 float4
    for (int id = t; id < 64 * 13; id += 256) {
        int p2 = id / 13;
        int j  = id - p2 * 13;
        int gy2 = ty * 8 + (p2 >> 3);
        int gx2 = tx * 8 + (p2 & 7);
        float4 v;
        v.x = corr_s[p2 * 53 + j * 4 + 0];
        v.y = corr_s[p2 * 53 + j * 4 + 1];
        v.z = corr_s[p2 * 53 + j * 4 + 2];
        v.w = corr_s[p2 * 53 + j * 4 + 3];
        *(float4*)(g_corr + ((size_t)b * HW + gy2 * WNUM + gx2) * 52 + j * 4) = v;
    }
}

// ---------------------------------------------------------------
// K3: vol = Wv@corr + bv, geometry, softmax, du/dv/conf.
// 4 thr x 16 logits, TWO pixels per thread: each Wvt float4 LDS feeds both
// pixels (halves the binding LDS stream per pixel). Quad lanes share the
// same pixel pair -> corr float4 loads broadcast.
// ---------------------------------------------------------------
__global__ __launch_bounds__(128) void k_final(const float* __restrict__ P_cur,
                                               const float* __restrict__ P_rnd,
                                               const float* __restrict__ Wv,
                                               const float* __restrict__ bv,
                                               const float* __restrict__ gamma_p,
                                               float* __restrict__ out) {
    __shared__ float Wvt[52 * 64];     // [d][e], d padded to 52, e padded to 64 (zeros)
    __shared__ float bvs[64];
    const int t = threadIdx.x;
    for (int id = t; id < 52 * 64; id += 128) {
        int d = id >> 6, e = id & 63;
        Wvt[id] = (e < 49 && d < 49) ? Wv[e * 49 + d] : 0.f;
    }
    if (t < 64) bvs[t] = (t < 49) ? bv[t] : -3.0e38f;
    __syncthreads();

    const int q  = t & 3;
    const int pl = t >> 2;                  // 0..31
    const int pix0 = blockIdx.x * 64 + pl * 2;   // even; pair never crosses batch
    const int pix1 = pix0 + 1;
    const int b   = pix0 / HW;
    const int hw0 = pix0 - b * HW;
    const int hw1 = hw0 + 1;
    const float gamma = *gamma_p;
    const int e0 = q * 16;

    const float* __restrict__ Pc = P_cur + (size_t)b * 3 * HW;
    const float* __restrict__ Pr = P_rnd + (size_t)b * 3 * HW;

    float l0[16], l1[16];
    {
        const int h0 = hw0 / WNUM, w0 = hw0 - h0 * WNUM;
        const float pcx = Pc[hw0], pcy = Pc[HW + hw0], pcz = Pc[2 * HW + hw0];
#pragma unroll
        for (int i = 0; i < 16; i++) {
            int e = e0 + i;
            if (e < 49) {
                int iy = e / 7, ix = e - iy * 7;
                int sy = h0 + iy - RAD, sx = w0 + ix - RAD;
                float prx = 0.f, pry = 0.f, prz = 0.f;
                if ((unsigned)sy < (unsigned)HNUM && (unsigned)sx < (unsigned)WNUM) {
                    int o = sy * WNUM + sx;
                    prx = Pr[o]; pry = Pr[HW + o]; prz = Pr[2 * HW + o];
                }
                float dx = pcx - prx, dy = pcy - pry, dz = pcz - prz;
                float ds = dx * dx + dy * dy + dz * dz;
                l0[i] = bvs[e] + gamma * (-sqrtf(fmaxf(ds, 1e-12f)) - 0.5f * fabsf(dz));
            } else l0[i] = -3.0e38f;
        }
    }
    {
        const int h1 = hw1 / WNUM, w1 = hw1 - h1 * WNUM;
        const float pcx = Pc[hw1], pcy = Pc[HW + hw1], pcz = Pc[2 * HW + hw1];
#pragma unroll
        for (int i = 0; i < 16; i++) {
            int e = e0 + i;
            if (e < 49) {
                int iy = e / 7, ix = e - iy * 7;
                int sy = h1 + iy - RAD, sx = w1 + ix - RAD;
                float prx = 0.f, pry = 0.f, prz = 0.f;
                if ((unsigned)sy < (unsigned)HNUM && (unsigned)sx < (unsigned)WNUM) {
                    int o = sy * WNUM + sx;
                    prx = Pr[o]; pry = Pr[HW + o]; prz = Pr[2 * HW + o];
                }
                float dx = pcx - prx, dy = pcy - pry, dz = pcz - prz;
                float ds = dx * dx + dy * dy + dz * dz;
                l1[i] = bvs[e] + gamma * (-sqrtf(fmaxf(ds, 1e-12f)) - 0.5f * fabsf(dz));
            } else l1[i] = -3.0e38f;
        }
    }

    const float4* __restrict__ ca = (const float4*)(g_corr + (size_t)pix0 * 52);
    const float4* __restrict__ cbp = (const float4*)(g_corr + (size_t)pix1 * 52);
#pragma unroll
    for (int j = 0; j < 13; j++) {
        float4 c4a = ca[j];
        float4 c4b = cbp[j];
        float cda[4] = {c4a.x, c4a.y, c4a.z, c4a.w};
        float cdb[4] = {c4b.x, c4b.y, c4b.z, c4b.w};
#pragma unroll
        for (int dd = 0; dd < 4; dd++) {
            int d = j * 4 + dd;
            float a = cda[dd], bb = cdb[dd];
            const float* wr = &Wvt[d * 64 + e0];
#pragma unroll
            for (int v4 = 0; v4 < 4; v4++) {
                float4 wv = *(const float4*)(wr + v4 * 4);
                l0[v4 * 4 + 0] += wv.x * a;  l1[v4 * 4 + 0] += wv.x * bb;
                l0[v4 * 4 + 1] += wv.y * a;  l1[v4 * 4 + 1] += wv.y * bb;
                l0[v4 * 4 + 2] += wv.z * a;  l1[v4 * 4 + 2] += wv.z * bb;
                l0[v4 * 4 + 3] += wv.w * a;  l1[v4 * 4 + 3] += wv.w * bb;
            }
        }
    }

    // softmax pixel 0
    {
        float m = l0[0];
#pragma unroll
        for (int i = 1; i < 16; i++) m = fmaxf(m, l0[i]);
        m = fmaxf(m, __shfl_xor_sync(0xffffffffu, m, 1));
        m = fmaxf(m, __shfl_xor_sync(0xffffffffu, m, 2));
        float S = 0.f, du = 0.f, dv = 0.f;
#pragma unroll
        for (int i = 0; i < 16; i++) {
            int e = e0 + i;
            float ex = (e < 49) ? __expf(l0[i] - m) : 0.f;
            S += ex;
            du += ex * (float)(e % 7 - 3);
            dv += ex * (float)(e / 7 - 3);
        }
        S  += __shfl_xor_sync(0xffffffffu, S, 1);
        S  += __shfl_xor_sync(0xffffffffu, S, 2);
        du += __shfl_xor_sync(0xffffffffu, du, 1);
        du += __shfl_xor_sync(0xffffffffu, du, 2);
        dv += __shfl_xor_sync(0xffffffffu, dv, 1);
        dv += __shfl_xor_sync(0xffffffffu, dv, 2);
        if (q == 0) {
            float inv = 1.f / S;
            out[pix0]                 = du * inv;
            out[BNUM * HW + pix0]     = dv * inv;
            out[2 * BNUM * HW + pix0] = inv;
        }
    }
    // softmax pixel 1
    {
        float m = l1[0];
#pragma unroll
        for (int i = 1; i < 16; i++) m = fmaxf(m, l1[i]);
        m = fmaxf(m, __shfl_xor_sync(0xffffffffu, m, 1));
        m = fmaxf(m, __shfl_xor_sync(0xffffffffu, m, 2));
        float S = 0.f, du = 0.f, dv = 0.f;
#pragma unroll
        for (int i = 0; i < 16; i++) {
            int e = e0 + i;
            float ex = (e < 49) ? __expf(l1[i] - m) : 0.f;
            S += ex;
            du += ex * (float)(e % 7 - 3);
            dv += ex * (float)(e / 7 - 3);
        }
        S  += __shfl_xor_sync(0xffffffffu, S, 1);
        S  += __shfl_xor_sync(0xffffffffu, S, 2);
        du += __shfl_xor_sync(0xffffffffu, du, 1);
        du += __shfl_xor_sync(0xffffffffu, du, 2);
        dv += __shfl_xor_sync(0xffffffffu, dv, 1);
        dv += __shfl_xor_sync(0xffffffffu, dv, 2);
        if (q == 0) {
            float inv = 1.f / S;
            out[pix1]                 = du * inv;
            out[BNUM * HW + pix1]     = dv * inv;
            out[2 * BNUM * HW + pix1] = inv;
        }
    }
}

// ---------------------------------------------------------------
extern "C" void kernel_launch(void* const* d_in, const int* in_sizes, int n_in,
                              void* d_out, int out_size) {
    const float* phi_cur = (const float*)d_in[0];
    const float* phi_rnd = (const float*)d_in[1];
    const float* P_cur   = (const float*)d_in[2];
    const float* P_rnd   = (const float*)d_in[3];
    const float* Wq      = (const float*)d_in[4];
    const float* Wk      = (const float*)d_in[5];
    const float* Wv      = (const float*)d_in[6];
    const float* bv      = (const float*)d_in[7];
    const float* gamma   = (const float*)d_in[8];
    float* out = (float*)d_out;

    cudaFuncSetAttribute(k_gemm, cudaFuncAttributeMaxDynamicSharedMemorySize, GEMM_SMEM);

    k_prep<<<128, 256>>>(Wq, Wk);
    k_gemm<<<dim3(HW / NT, BNUM, 2), 256, GEMM_SMEM>>>(phi_cur, phi_rnd);
    k_corr<<<dim3(WNUM / 8, HNUM / 8, BNUM), 256>>>();
    k_final<<<(BNUM * HW) / 64, 128>>>(P_cur, P_rnd, Wv, bv, gamma, out);
}

// round 13
// speedup vs baseline: 1.6051x; 1.0829x over previous
#include <cuda_runtime.h>
#include <cuda_bf16.h>
#include <cstdint>

#define HNUM 112
#define WNUM 112
#define HW   12544      // 112*112
#define BNUM 2
#define CIN  256
#define CMID 128
#define DNUM 49
#define RAD  3

#define NT 128          // pixel (N) tile in GEMM
#define KC 64           // K chunk

#if defined(__CUDA_ARCH_FEAT_SM103_ALL) || defined(__CUDA_ARCH_FEAT_SM100_ALL) || defined(__CUDA_ARCH_FEAT_SM101_ALL)
#define HAS_TCGEN05 1
#endif

// -------- scratch (no allocations allowed) --------
__device__ __nv_bfloat16 g_Ah[2][CMID * CIN];          // [tensor][m][k] bf16 hi
__device__ __nv_bfloat16 g_Al[2][CMID * CIN];          // [tensor][m][k] bf16 lo
__device__ float g_qk[2][(size_t)BNUM * HW * CMID];    // [tensor][b*HW][128], l2-normalized
__device__ float g_corr[(size_t)BNUM * HW * 52];       // [b][hw][52] pixel-major, d 49..51 = 0

// ================= helpers =================
__device__ __forceinline__ uint32_t smem_u32(const void* p) {
    uint32_t a;
    asm("{ .reg .u64 t; cvta.to.shared.u64 t, %1; cvt.u32.u64 %0, t; }" : "=r"(a) : "l"(p));
    return a;
}
#define SW128(o) ((o) ^ (((o) >> 3) & 0x70))

#define CVT_BF16X2(res, x0, x1) \
    asm("cvt.rn.satfinite.bf16x2.f32 %0, %1, %2;" : "=r"(res) : "f"(x1), "f"(x0))

#define STS128(addr, a, b, c, d) \
    asm volatile("st.shared.v4.b32 [%0], {%1,%2,%3,%4};" \
                 :: "r"(addr), "r"(a), "r"(b), "r"(c), "r"(d))

#ifdef HAS_TCGEN05
__device__ __forceinline__ uint32_t elect_one() {
    uint32_t pred;
    asm volatile("{ .reg .pred p; elect.sync _|p, 0xFFFFFFFF; selp.b32 %0, 1, 0, p; }" : "=r"(pred));
    return pred;
}

static constexpr uint64_t DESC_BASE_SW128 =
    (uint64_t(2) << 61) | (uint64_t(1) << 46) | (uint64_t(64) << 32) | (uint64_t(1) << 16);
__device__ __forceinline__ uint64_t make_desc(uint32_t addr) {
    return DESC_BASE_SW128 | ((uint64_t)(addr >> 4) & 0x3FFF);
}

// idesc: dtype=F32, atype=btype=BF16, N=128, M=128
static constexpr uint32_t GEMM_IDESC =
    (1u << 4) | (1u << 7) | (1u << 10) | ((128u / 8) << 17) | ((128u / 16) << 24);

__device__ __forceinline__ void mma_f16_ss(uint32_t d, uint64_t ad, uint64_t bd,
                                           uint32_t idesc, uint32_t en) {
    asm volatile(
        "{\n\t.reg .pred p;\n\t"
        "setp.ne.u32 p, %4, 0;\n\t"
        "tcgen05.mma.cta_group::1.kind::f16 [%0], %1, %2, %3, {%5,%5,%5,%5}, p;\n\t}"
        :: "r"(d), "l"(ad), "l"(bd), "r"(idesc), "r"(en), "r"(0u) : "memory");
}

#define TC_ALLOC(sm_addr, ncols) \
    asm volatile("tcgen05.alloc.cta_group::1.sync.aligned.shared::cta.b32 [%0], %1;" \
                 :: "r"(sm_addr), "r"((uint32_t)(ncols)) : "memory")
#define TC_DEALLOC(tm, ncols) \
    asm volatile("tcgen05.dealloc.cta_group::1.sync.aligned.b32 %0, %1;" :: "r"(tm), "r"((uint32_t)(ncols)))
#define TC_RELINQ() asm volatile("tcgen05.relinquish_alloc_permit.cta_group::1.sync.aligned;")
#define TC_COMMIT(mbar) \
    asm volatile("tcgen05.commit.cta_group::1.mbarrier::arrive::one.shared::cluster.b64 [%0];" \
                 :: "r"(mbar) : "memory")
#define TC_FENCE_AFTER()  asm volatile("tcgen05.fence::after_thread_sync;" ::: "memory")
#define TC_FENCE_BEFORE() asm volatile("tcgen05.fence::before_thread_sync;" ::: "memory")
#define TC_WAIT_LD()      asm volatile("tcgen05.wait::ld.sync.aligned;" ::: "memory")
// generic-proxy smem writes -> async-proxy (tcgen05 MMA) visibility. REQUIRED.
#define FENCE_PROXY_ASYNC() asm volatile("fence.proxy.async.shared::cta;" ::: "memory")

#define MBAR_INIT(a, n) \
    asm volatile("mbarrier.init.shared.b64 [%0], %1;" :: "r"(a), "r"((uint32_t)(n)) : "memory")

#define MBAR_WAIT(mbar_addr, par) do {                                              \
    uint32_t _m = (mbar_addr), _p = (par), _done;                                   \
    asm volatile("{ .reg .pred p; mbarrier.try_wait.parity.acquire.cta.shared::cta.b64 p, [%1], %2; selp.b32 %0, 1, 0, p; }" \
        : "=r"(_done) : "r"(_m), "r"(_p) : "memory");                               \
    if (!_done) {                                                                   \
        asm volatile("{ .reg .pred P1; WL_%=: mbarrier.try_wait.parity.acquire.cta.shared::cta.b64 P1, [%0], %1, 0x989680; @P1 bra.uni WD_%=; bra.uni WL_%=; WD_%=: }" \
            :: "r"(_m), "r"(_p) : "memory");                                        \
    }                                                                               \
} while (0)

#define LDTM_X32(r, addr) \
    asm volatile("tcgen05.ld.sync.aligned.32x32b.x32.b32 " \
        "{%0,%1,%2,%3,%4,%5,%6,%7,%8,%9,%10,%11,%12,%13,%14,%15," \
        "%16,%17,%18,%19,%20,%21,%22,%23,%24,%25,%26,%27,%28,%29,%30,%31}, [%32];" \
        : "=r"((r)[0]),"=r"((r)[1]),"=r"((r)[2]),"=r"((r)[3]),"=r"((r)[4]),"=r"((r)[5]),"=r"((r)[6]),"=r"((r)[7]), \
          "=r"((r)[8]),"=r"((r)[9]),"=r"((r)[10]),"=r"((r)[11]),"=r"((r)[12]),"=r"((r)[13]),"=r"((r)[14]),"=r"((r)[15]), \
          "=r"((r)[16]),"=r"((r)[17]),"=r"((r)[18]),"=r"((r)[19]),"=r"((r)[20]),"=r"((r)[21]),"=r"((r)[22]),"=r"((r)[23]), \
          "=r"((r)[24]),"=r"((r)[25]),"=r"((r)[26]),"=r"((r)[27]),"=r"((r)[28]),"=r"((r)[29]),"=r"((r)[30]),"=r"((r)[31]) \
        : "r"(addr))
#endif // HAS_TCGEN05

// ---------------------------------------------------------------
// K0: split Wq/Wk into bf16 hi/lo ([m][k], k contiguous)
// ---------------------------------------------------------------
__global__ void k_prep(const float* __restrict__ Wq, const float* __restrict__ Wk) {
    int id = blockIdx.x * blockDim.x + threadIdx.x;
    if (id < CMID * CIN) {
        float a = Wq[id];
        __nv_bfloat16 h = __float2bfloat16_rn(a);
        g_Ah[0][id] = h;
        g_Al[0][id] = __float2bfloat16_rn(a - __bfloat162float(h));
        float b = Wk[id];
        __nv_bfloat16 h2 = __float2bfloat16_rn(b);
        g_Ah[1][id] = h2;
        g_Al[1][id] = __float2bfloat16_rn(b - __bfloat162float(h2));
    }
}

// ---------------------------------------------------------------
// K1: projection GEMM + fused per-pixel l2norm.
// Staging vectorized to STS.128: A thread = (row m=t>>1, half qh), 4 v4
// stores per buffer; B thread = (pixel p=t&127, 32 c's) packed bf16x2, 4 v4
// stores per buffer. 16 STS/thread/chunk vs 96 scalar before.
// ---------------------------------------------------------------
#define GEMM_SMEM 67584

__global__ __launch_bounds__(256) void k_gemm(const float* __restrict__ phi_cur,
                                              const float* __restrict__ phi_rnd) {
    extern __shared__ char smraw[];
    const int t = threadIdx.x;
    const int tsel = blockIdx.z, b = blockIdx.y;
    const int p0 = blockIdx.x * NT;

    const float* __restrict__ X = (tsel ? phi_rnd : phi_cur) + (size_t)b * CIN * HW;
    const __nv_bfloat16* __restrict__ Agh = g_Ah[tsel];
    const __nv_bfloat16* __restrict__ Agl = g_Al[tsel];

#ifdef HAS_TCGEN05
    const uint32_t sraw = smem_u32(smraw);
    const uint32_t sb = (sraw + 1023) & ~1023u;
    float* tb = (float*)(smraw + (sb - sraw));        // epilogue transpose buffer

    const uint32_t Ah = sb, Al = sb + 16384, Bh = sb + 32768, Bl = sb + 49152;
    const uint32_t HDR = sb + 66304;                  // tmem ptr
    const uint32_t MBAR = HDR + 8;
    const int wid = t >> 5;

    if (t == 0) MBAR_INIT(MBAR, 1);
    if (wid == 0) TC_ALLOC(HDR, 128);
    __syncthreads();
    uint32_t tmem;
    asm volatile("ld.shared.b32 %0, [%1];" : "=r"(tmem) : "r"(HDR));

    // A staging identity: row m = t>>1, u32-half qh = (t&1)*16 (u32 units)
    const int am = t >> 1;
    const int aq = (t & 1) * 16;           // u32 index within the 32-u32 row
    // B staging identity: pixel p = t&127, c-quarter c0t = (t>>7)*32 (bf16 units)
    const int bp = t & 127;
    const int bc = (t >> 7) * 32;

    uint4 avh[4], avl[4];      // prefetched A hi/lo (16 u32 each)
    float bx[32];              // prefetched X values

    // ---- prefetch chunk 0 ----
    {
        const uint4* ah4 = (const uint4*)(Agh + am * CIN + 0 + aq * 2);
        const uint4* al4 = (const uint4*)(Agl + am * CIN + 0 + aq * 2);
#pragma unroll
        for (int g = 0; g < 4; g++) { avh[g] = ah4[g]; avl[g] = al4[g]; }
#pragma unroll
        for (int j = 0; j < 32; j++)
            bx[j] = X[(size_t)(bc + j) * HW + p0 + bp];
    }

    for (int ch = 0; ch < CIN / KC; ch++) {
        if (ch > 0) MBAR_WAIT(MBAR, (ch - 1) & 1);

        // ---- A: 4 STS.128 per buffer ----
#pragma unroll
        for (int g = 0; g < 4; g++) {
            uint32_t off = SW128((uint32_t)(am * 128 + aq * 4 + g * 16));
            STS128(Ah + off, avh[g].x, avh[g].y, avh[g].z, avh[g].w);
            STS128(Al + off, avl[g].x, avl[g].y, avl[g].z, avl[g].w);
        }
        // ---- B: pack bf16x2, 4 STS.128 per buffer ----
#pragma unroll
        for (int g = 0; g < 4; g++) {
            uint32_t hp[4], lp[4];
#pragma unroll
            for (int u = 0; u < 4; u++) {
                int jj = g * 4 + u;                 // u32 index 0..15
                float x0 = bx[2 * jj], x1 = bx[2 * jj + 1];
                uint32_t h;
                CVT_BF16X2(h, x0, x1);
                float h0f = __uint_as_float(h << 16);
                float h1f = __uint_as_float(h & 0xffff0000u);
                uint32_t l;
                CVT_BF16X2(l, x0 - h0f, x1 - h1f);
                hp[u] = h; lp[u] = l;
            }
            uint32_t off = SW128((uint32_t)(bp * 128 + bc * 2 + g * 16));
            STS128(Bh + off, hp[0], hp[1], hp[2], hp[3]);
            STS128(Bl + off, lp[0], lp[1], lp[2], lp[3]);
        }
        FENCE_PROXY_ASYNC();
        __syncthreads();

        if (wid == 0 && elect_one()) {
            uint64_t adh = make_desc(Ah), adl = make_desc(Al);
            uint64_t bdh = make_desc(Bh), bdl = make_desc(Bl);
#pragma unroll
            for (int ks = 0; ks < 4; ks++) {   // K=16 per MMA
                uint32_t en0 = (ch > 0 || ks > 0) ? 1u : 0u;
                mma_f16_ss(tmem, adh + ks * 2, bdh + ks * 2, GEMM_IDESC, en0);
                mma_f16_ss(tmem, adh + ks * 2, bdl + ks * 2, GEMM_IDESC, 1u);
                mma_f16_ss(tmem, adl + ks * 2, bdh + ks * 2, GEMM_IDESC, 1u);
            }
            TC_COMMIT(MBAR);
        }

        // ---- prefetch next chunk while this chunk's MMA runs ----
        if (ch < CIN / KC - 1) {
            const int c0n = (ch + 1) * KC;
            const uint4* ah4 = (const uint4*)(Agh + am * CIN + c0n + aq * 2);
            const uint4* al4 = (const uint4*)(Agl + am * CIN + c0n + aq * 2);
#pragma unroll
            for (int g = 0; g < 4; g++) { avh[g] = ah4[g]; avl[g] = al4[g]; }
#pragma unroll
            for (int j = 0; j < 32; j++)
                bx[j] = X[(size_t)(c0n + bc + j) * HW + p0 + bp];
        }
    }
    MBAR_WAIT(MBAR, (CIN / KC - 1) & 1);

    // ---- epilogue: LDTM -> smem transpose -> per-pixel l2norm -> pixel-major out ----
    TC_FENCE_AFTER();
    const int sub = wid & 3, half = wid >> 2;
    const int lane = t & 31;
    const int m = sub * 32 + lane;

    uint32_t d0[32], d1[32];
    LDTM_X32(d0, tmem + half * 64);
    LDTM_X32(d1, tmem + half * 64 + 32);
    TC_WAIT_LD();
    TC_FENCE_BEFORE();
    __syncthreads();     // stage buffers dead; tb overwrites them

#pragma unroll
    for (int j = 0; j < 32; j++) tb[m * 129 + half * 64 + j]      = __uint_as_float(d0[j]);
#pragma unroll
    for (int j = 0; j < 32; j++) tb[m * 129 + half * 64 + 32 + j] = __uint_as_float(d1[j]);
    __syncthreads();

    {
        const int p = t >> 1, hh = t & 1;
        float s = 0.f;
#pragma unroll
        for (int mm = 0; mm < 64; mm++) {
            float v = tb[(hh * 64 + mm) * 129 + p];
            s += v * v;
        }
        s += __shfl_xor_sync(0xffffffffu, s, 1);
        float sc = 1.f / fmaxf(sqrtf(s), 1e-12f);
        float* OUT = g_qk[tsel] + ((size_t)b * HW + p0 + p) * CMID + hh * 64;
#pragma unroll
        for (int j = 0; j < 64; j += 4) {
            float4 v;
            v.x = tb[(hh * 64 + j + 0) * 129 + p] * sc;
            v.y = tb[(hh * 64 + j + 1) * 129 + p] * sc;
            v.z = tb[(hh * 64 + j + 2) * 129 + p] * sc;
            v.w = tb[(hh * 64 + j + 3) * 129 + p] * sc;
            *(float4*)(OUT + j) = v;
        }
    }
    __syncthreads();
    if (wid == 0) {
        TC_RELINQ();
        TC_DEALLOC(tmem, 128);
    }
#else
    // ---------- SIMT fallback (generic gencode pass; not selected on GB300) ----------
    float* Ws = (float*)smraw;
    float* Xs = Ws + 16 * 128;
    float* red = Xs + 16 * 128;
    float* scale_s = red + 16 * 128;

    const int to = t >> 4, tp = t & 15;
    const int m0 = to * 8, q0 = tp * 8;

    float acc[8][8];
#pragma unroll
    for (int i = 0; i < 8; i++)
#pragma unroll
        for (int j = 0; j < 8; j++) acc[i][j] = 0.f;

    for (int c0 = 0; c0 < CIN; c0 += 16) {
#pragma unroll
        for (int i = 0; i < 8; i++) {
            int id = t + i * 256;
            int c = id >> 7, m = id & 127;
            Ws[c * 128 + m] = __bfloat162float(Agh[m * CIN + c0 + c]) +
                              __bfloat162float(Agl[m * CIN + c0 + c]);
            Xs[c * 128 + m] = X[(size_t)(c0 + c) * HW + p0 + m];
        }
        __syncthreads();
#pragma unroll
        for (int cc = 0; cc < 16; cc++) {
            float wv[8], xv[8];
#pragma unroll
            for (int i = 0; i < 8; i++) wv[i] = Ws[cc * 128 + m0 + i];
#pragma unroll
            for (int j = 0; j < 8; j++) xv[j] = Xs[cc * 128 + q0 + j];
#pragma unroll
            for (int i = 0; i < 8; i++)
#pragma unroll
                for (int j = 0; j < 8; j++) acc[i][j] += wv[i] * xv[j];
        }
        __syncthreads();
    }

#pragma unroll
    for (int j = 0; j < 8; j++) {
        float s = 0.f;
#pragma unroll
        for (int i = 0; i < 8; i++) s += acc[i][j] * acc[i][j];
        red[to * 128 + q0 + j] = s;
    }
    __syncthreads();
    if (t < 128) {
        float n = 0.f;
#pragma unroll
        for (int g = 0; g < 16; g++) n += red[g * 128 + t];
        scale_s[t] = 1.f / fmaxf(sqrtf(n), 1e-12f);
    }
    __syncthreads();

#pragma unroll
    for (int j = 0; j < 8; j++) {
        float sc = scale_s[q0 + j];
        float* dst = g_qk[tsel] + ((size_t)b * HW + p0 + q0 + j) * CMID + m0;
#pragma unroll
        for (int i = 0; i < 8; i++) dst[i] = acc[i][j] * sc;
    }
#endif
}

// ---------------------------------------------------------------
// K2: local correlation. QUAD layout (pix = t>>2, grp = t&3); q shared
// via width-4 shfl. Output pixel-major [b][hw][52].
// ---------------------------------------------------------------
__global__ __launch_bounds__(256) void k_corr() {
    const int tx = blockIdx.x, ty = blockIdx.y, b = blockIdx.z;
    const int t   = threadIdx.x;
    const int pix = t >> 2;
    const int grp = t & 3;
    const int px  = pix & 7;
    const int py  = pix >> 3;

    __shared__ float ks[16][196];
    __shared__ float corr_s[64 * 53];

    const float* __restrict__ Q = g_qk[0] + (size_t)b * HW * CMID;
    const float* __restrict__ K = g_qk[1] + (size_t)b * HW * CMID;

    const int gx = tx * 8 + px;
    const int gy = ty * 8 + py;
    const int pb = py * 14 + px;

    int addr[13];
#pragma unroll
    for (int k = 0; k < 13; k++) {
        int d  = grp + 4 * k;
        int dd = (d < DNUM) ? d : 0;
        addr[k] = pb + (dd / 7) * 14 + (dd % 7);
    }

    float acc[13];
#pragma unroll
    for (int k = 0; k < 13; k++) acc[k] = 0.f;

    const float* __restrict__ qptr = Q + (size_t)(gy * WNUM + gx) * CMID;

    for (int c0 = 0; c0 < CMID; c0 += 16) {
#pragma unroll
        for (int i = 0; i < 4; i++) {
            int id = t + i * 256;
            if (id < 784) {
                int hp = id >> 2;
                int cv = id & 3;
                int hy = hp / 14, hx = hp - hy * 14;
                int sy = ty * 8 + hy - RAD;
                int sx = tx * 8 + hx - RAD;
                float4 v = make_float4(0.f, 0.f, 0.f, 0.f);
                if ((unsigned)sy < (unsigned)HNUM && (unsigned)sx < (unsigned)WNUM)
                    v = *(const float4*)(K + (size_t)(sy * WNUM + sx) * CMID + c0 + cv * 4);
                ks[cv * 4 + 0][hp] = v.x;
                ks[cv * 4 + 1][hp] = v.y;
                ks[cv * 4 + 2][hp] = v.z;
                ks[cv * 4 + 3][hp] = v.w;
            }
        }
        __syncthreads();

        float4 qv = *(const float4*)(qptr + c0 + grp * 4);
        float qa[4] = {qv.x, qv.y, qv.z, qv.w};

#pragma unroll
        for (int cc = 0; cc < 16; cc++) {
            float qc = __shfl_sync(0xffffffffu, qa[cc & 3], cc >> 2, 4);
#pragma unroll
            for (int k = 0; k < 13; k++)
                acc[k] += qc * ks[cc][addr[k]];
        }
        __syncthreads();
    }

#pragma unroll
    for (int k = 0; k < 13; k++) {
        int d = grp + 4 * k;
        if (d < DNUM)
            corr_s[pix * 53 + d] = acc[k];
    }
    if (t < 192) corr_s[(t / 3) * 53 + 49 + (t % 3)] = 0.f;
    __syncthreads();

    for (int id = t; id < 64 * 13; id += 256) {
        int p2 = id / 13;
        int j  = id - p2 * 13;
        int gy2 = ty * 8 + (p2 >> 3);
        int gx2 = tx * 8 + (p2 & 7);
        float4 v;
        v.x = corr_s[p2 * 53 + j * 4 + 0];
        v.y = corr_s[p2 * 53 + j * 4 + 1];
        v.z = corr_s[p2 * 53 + j * 4 + 2];
        v.w = corr_s[p2 * 53 + j * 4 + 3];
        *(float4*)(g_corr + ((size_t)b * HW + gy2 * WNUM + gx2) * 52 + j * 4) = v;
    }
}

// ---------------------------------------------------------------
// K3: vol = Wv@corr + bv, geometry, softmax, du/dv/conf.
// 4 thr x 16 logits, two pixels per thread (Wvt LDS amortized).
// ---------------------------------------------------------------
__global__ __launch_bounds__(128) void k_final(const float* __restrict__ P_cur,
                                               const float* __restrict__ P_rnd,
                                               const float* __restrict__ Wv,
                                               const float* __restrict__ bv,
                                               const float* __restrict__ gamma_p,
                                               float* __restrict__ out) {
    __shared__ float Wvt[52 * 64];
    __shared__ float bvs[64];
    const int t = threadIdx.x;
    for (int id = t; id < 52 * 64; id += 128) {
        int d = id >> 6, e = id & 63;
        Wvt[id] = (e < 49 && d < 49) ? Wv[e * 49 + d] : 0.f;
    }
    if (t < 64) bvs[t] = (t < 49) ? bv[t] : -3.0e38f;
    __syncthreads();

    const int q  = t & 3;
    const int pl = t >> 2;
    const int pix0 = blockIdx.x * 64 + pl * 2;
    const int pix1 = pix0 + 1;
    const int b   = pix0 / HW;
    const int hw0 = pix0 - b * HW;
    const int hw1 = hw0 + 1;
    const float gamma = *gamma_p;
    const int e0 = q * 16;

    const float* __restrict__ Pc = P_cur + (size_t)b * 3 * HW;
    const float* __restrict__ Pr = P_rnd + (size_t)b * 3 * HW;

    float l0[16], l1[16];
    {
        const int h0 = hw0 / WNUM, w0 = hw0 - h0 * WNUM;
        const float pcx = Pc[hw0], pcy = Pc[HW + hw0], pcz = Pc[2 * HW + hw0];
#pragma unroll
        for (int i = 0; i < 16; i++) {
            int e = e0 + i;
            if (e < 49) {
                int iy = e / 7, ix = e - iy * 7;
                int sy = h0 + iy - RAD, sx = w0 + ix - RAD;
                float prx = 0.f, pry = 0.f, prz = 0.f;
                if ((unsigned)sy < (unsigned)HNUM && (unsigned)sx < (unsigned)WNUM) {
                    int o = sy * WNUM + sx;
                    prx = Pr[o]; pry = Pr[HW + o]; prz = Pr[2 * HW + o];
                }
                float dx = pcx - prx, dy = pcy - pry, dz = pcz - prz;
                float ds = dx * dx + dy * dy + dz * dz;
                l0[i] = bvs[e] + gamma * (-sqrtf(fmaxf(ds, 1e-12f)) - 0.5f * fabsf(dz));
            } else l0[i] = -3.0e38f;
        }
    }
    {
        const int h1 = hw1 / WNUM, w1 = hw1 - h1 * WNUM;
        const float pcx = Pc[hw1], pcy = Pc[HW + hw1], pcz = Pc[2 * HW + hw1];
#pragma unroll
        for (int i = 0; i < 16; i++) {
            int e = e0 + i;
            if (e < 49) {
                int iy = e / 7, ix = e - iy * 7;
                int sy = h1 + iy - RAD, sx = w1 + ix - RAD;
                float prx = 0.f, pry = 0.f, prz = 0.f;
                if ((unsigned)sy < (unsigned)HNUM && (unsigned)sx < (unsigned)WNUM) {
                    int o = sy * WNUM + sx;
                    prx = Pr[o]; pry = Pr[HW + o]; prz = Pr[2 * HW + o];
                }
                float dx = pcx - prx, dy = pcy - pry, dz = pcz - prz;
                float ds = dx * dx + dy * dy + dz * dz;
                l1[i] = bvs[e] + gamma * (-sqrtf(fmaxf(ds, 1e-12f)) - 0.5f * fabsf(dz));
            } else l1[i] = -3.0e38f;
        }
    }

    const float4* __restrict__ ca = (const float4*)(g_corr + (size_t)pix0 * 52);
    const float4* __restrict__ cbp = (const float4*)(g_corr + (size_t)pix1 * 52);
#pragma unroll
    for (int j = 0; j < 13; j++) {
        float4 c4a = ca[j];
        float4 c4b = cbp[j];
        float cda[4] = {c4a.x, c4a.y, c4a.z, c4a.w};
        float cdb[4] = {c4b.x, c4b.y, c4b.z, c4b.w};
#pragma unroll
        for (int dd = 0; dd < 4; dd++) {
            int d = j * 4 + dd;
            float a = cda[dd], bb = cdb[dd];
            const float* wr = &Wvt[d * 64 + e0];
#pragma unroll
            for (int v4 = 0; v4 < 4; v4++) {
                float4 wv = *(const float4*)(wr + v4 * 4);
                l0[v4 * 4 + 0] += wv.x * a;  l1[v4 * 4 + 0] += wv.x * bb;
                l0[v4 * 4 + 1] += wv.y * a;  l1[v4 * 4 + 1] += wv.y * bb;
                l0[v4 * 4 + 2] += wv.z * a;  l1[v4 * 4 + 2] += wv.z * bb;
                l0[v4 * 4 + 3] += wv.w * a;  l1[v4 * 4 + 3] += wv.w * bb;
            }
        }
    }

    {
        float m = l0[0];
#pragma unroll
        for (int i = 1; i < 16; i++) m = fmaxf(m, l0[i]);
        m = fmaxf(m, __shfl_xor_sync(0xffffffffu, m, 1));
        m = fmaxf(m, __shfl_xor_sync(0xffffffffu, m, 2));
        float S = 0.f, du = 0.f, dv = 0.f;
#pragma unroll
        for (int i = 0; i < 16; i++) {
            int e = e0 + i;
            float ex = (e < 49) ? __expf(l0[i] - m) : 0.f;
            S += ex;
            du += ex * (float)(e % 7 - 3);
            dv += ex * (float)(e / 7 - 3);
        }
        S  += __shfl_xor_sync(0xffffffffu, S, 1);
        S  += __shfl_xor_sync(0xffffffffu, S, 2);
        du += __shfl_xor_sync(0xffffffffu, du, 1);
        du += __shfl_xor_sync(0xffffffffu, du, 2);
        dv += __shfl_xor_sync(0xffffffffu, dv, 1);
        dv += __shfl_xor_sync(0xffffffffu, dv, 2);
        if (q == 0) {
            float inv = 1.f / S;
            out[pix0]                 = du * inv;
            out[BNUM * HW + pix0]     = dv * inv;
            out[2 * BNUM * HW + pix0] = inv;
        }
    }
    {
        float m = l1[0];
#pragma unroll
        for (int i = 1; i < 16; i++) m = fmaxf(m, l1[i]);
        m = fmaxf(m, __shfl_xor_sync(0xffffffffu, m, 1));
        m = fmaxf(m, __shfl_xor_sync(0xffffffffu, m, 2));
        float S = 0.f, du = 0.f, dv = 0.f;
#pragma unroll
        for (int i = 0; i < 16; i++) {
            int e = e0 + i;
            float ex = (e < 49) ? __expf(l1[i] - m) : 0.f;
            S += ex;
            du += ex * (float)(e % 7 - 3);
            dv += ex * (float)(e / 7 - 3);
        }
        S  += __shfl_xor_sync(0xffffffffu, S, 1);
        S  += __shfl_xor_sync(0xffffffffu, S, 2);
        du += __shfl_xor_sync(0xffffffffu, du, 1);
        du += __shfl_xor_sync(0xffffffffu, du, 2);
        dv += __shfl_xor_sync(0xffffffffu, dv, 1);
        dv += __shfl_xor_sync(0xffffffffu, dv, 2);
        if (q == 0) {
            float inv = 1.f / S;
            out[pix1]                 = du * inv;
            out[BNUM * HW + pix1]     = dv * inv;
            out[2 * BNUM * HW + pix1] = inv;
        }
    }
}

// ---------------------------------------------------------------
extern "C" void kernel_launch(void* const* d_in, const int* in_sizes, int n_in,
                              void* d_out, int out_size) {
    const float* phi_cur = (const float*)d_in[0];
    const float* phi_rnd = (const float*)d_in[1];
    const float* P_cur   = (const float*)d_in[2];
    const float* P_rnd   = (const float*)d_in[3];
    const float* Wq      = (const float*)d_in[4];
    const float* Wk      = (const float*)d_in[5];
    const float* Wv      = (const float*)d_in[6];
    const float* bv      = (const float*)d_in[7];
    const float* gamma   = (const float*)d_in[8];
    float* out = (float*)d_out;

    cudaFuncSetAttribute(k_gemm, cudaFuncAttributeMaxDynamicSharedMemorySize, GEMM_SMEM);

    k_prep<<<128, 256>>>(Wq, Wk);
    k_gemm<<<dim3(HW / NT, BNUM, 2), 256, GEMM_SMEM>>>(phi_cur, phi_rnd);
    k_corr<<<dim3(WNUM / 8, HNUM / 8, BNUM), 256>>>();
    k_final<<<(BNUM * HW) / 64, 128>>>(P_cur, P_rnd, Wv, bv, gamma, out);
}